// round 4
// baseline (speedup 1.0000x reference)
#include <cuda_runtime.h>
#include <math.h>

// ---------------- scratch (static device globals: allocation-free) ----------------
__device__ float g_mod[4 * 9216];                 // (b,half) x 9*1024
__device__ float g_xln[4096 * 1024];              // LN+mod output
__device__ float g_qkv[4096 * 3072];              // qkv projections
__device__ float g_scores[67108864];              // 64 x 1024 x 1024 attention probs
__device__ float g_attnout[4096 * 1024];          // attention output (s,n,h*64+d)
__device__ float g_hbuf[4096 * 4096];             // MLP hidden

// ---------------- reduction helpers ----------------
__device__ __forceinline__ float warpSum(float v) {
    #pragma unroll
    for (int o = 16; o > 0; o >>= 1) v += __shfl_xor_sync(0xffffffffu, v, o);
    return v;
}
__device__ __forceinline__ float warpMax(float v) {
    #pragma unroll
    for (int o = 16; o > 0; o >>= 1) v = fmaxf(v, __shfl_xor_sync(0xffffffffu, v, o));
    return v;
}

// ---------------- adaLN modulation: mod[bj] = silu(c[bj]) @ ada_w + ada_b ----------------
__global__ void mod_kernel(const float* __restrict__ c,
                           const float* __restrict__ ada_w,
                           const float* __restrict__ ada_b) {
    __shared__ float sc[1024];
    int bj = blockIdx.y;                       // 0..3 = b*2+j
    int o  = blockIdx.x * 256 + threadIdx.x;   // 0..9215
    const float* crow = c + bj * 1024;
    for (int i = threadIdx.x; i < 1024; i += 256) {
        float v = crow[i];
        sc[i] = v / (1.f + __expf(-v));
    }
    __syncthreads();
    float acc = 0.f;
    #pragma unroll 4
    for (int k = 0; k < 1024; k++)
        acc = fmaf(sc[k], ada_w[(size_t)k * 9216 + o], acc);
    g_mod[bj * 9216 + o] = acc + ada_b[o];
}

// ---------------- fused LayerNorm + modulation (one block per token row) ----------------
__global__ void ln_mod_kernel(const float* __restrict__ x, float* __restrict__ y, int shOff) {
    int r = blockIdx.x;            // 0..4095
    int s = r >> 10;               // seq = b*2+half
    int t = threadIdx.x;           // 256 threads, float4 each
    const float4* xr = (const float4*)(x + (size_t)r * 1024);
    float4 v = xr[t];
    __shared__ float sm[8];
    float ws = warpSum(v.x + v.y + v.z + v.w);
    if ((t & 31) == 0) sm[t >> 5] = ws;
    __syncthreads();
    float mu;
    { float s8 = 0.f;
      #pragma unroll
      for (int i = 0; i < 8; i++) s8 += sm[i];
      mu = s8 * (1.f / 1024.f); }
    __syncthreads();
    float dx = v.x - mu, dy = v.y - mu, dz = v.z - mu, dw = v.w - mu;
    float wv = warpSum(dx*dx + dy*dy + dz*dz + dw*dw);
    if ((t & 31) == 0) sm[t >> 5] = wv;
    __syncthreads();
    float var;
    { float s8 = 0.f;
      #pragma unroll
      for (int i = 0; i < 8; i++) s8 += sm[i];
      var = s8 * (1.f / 1024.f); }
    float inv = rsqrtf(var + 1e-6f);
    const float* m = g_mod + s * 9216 + shOff;
    float4 shv = *(const float4*)(m + t * 4);
    float4 scv = *(const float4*)(m + 1024 + t * 4);
    float4 o;
    o.x = dx * inv * (1.f + scv.x) + shv.x;
    o.y = dy * inv * (1.f + scv.y) + shv.y;
    o.z = dz * inv * (1.f + scv.z) + shv.z;
    o.w = dw * inv * (1.f + scv.w) + shv.w;
    ((float4*)(y + (size_t)r * 1024))[t] = o;
}

// ---------------- 128x128x8 SGEMM, C = A(MxK) @ B(KxN), epilogue by MODE ----------------
// MODE 0: C = acc + bias
// MODE 1: C = gelu_tanh(acc + bias)
// MODE 2: C = base + gate[(row>>10)*9216 + gOff + col] * (acc + bias)
template <int MODE>
__global__ void __launch_bounds__(256, 2)
sgemm128(const float* __restrict__ A, const float* __restrict__ B,
         float* __restrict__ C, int K, int N,
         const float* __restrict__ bias,
         const float* __restrict__ base, int gOff) {
    __shared__ float As[8][128];
    __shared__ float Bs[8][128];
    int tid = threadIdx.x;
    int brow = blockIdx.y * 128, bcol = blockIdx.x * 128;
    int ty = tid >> 4, tx = tid & 15;
    int arow = tid >> 1, ak = (tid & 1) * 4;
    int bk = tid >> 5, bcl = (tid & 31) * 4;
    const float* Aptr = A + (size_t)(brow + arow) * K + ak;
    const float* Bptr = B + (size_t)bk * N + bcol + bcl;
    float acc[8][8];
    #pragma unroll
    for (int i = 0; i < 8; i++)
        #pragma unroll
        for (int j = 0; j < 8; j++) acc[i][j] = 0.f;

    for (int k0 = 0; k0 < K; k0 += 8) {
        float4 av = *(const float4*)(Aptr + k0);
        As[ak + 0][arow] = av.x; As[ak + 1][arow] = av.y;
        As[ak + 2][arow] = av.z; As[ak + 3][arow] = av.w;
        float4 bv = *(const float4*)(Bptr + (size_t)k0 * N);
        *(float4*)&Bs[bk][bcl] = bv;
        __syncthreads();
        #pragma unroll
        for (int k = 0; k < 8; k++) {
            float ra[8], rb[8];
            #pragma unroll
            for (int i = 0; i < 8; i++) ra[i] = As[k][ty * 8 + i];
            #pragma unroll
            for (int j = 0; j < 8; j++) rb[j] = Bs[k][tx * 8 + j];
            #pragma unroll
            for (int i = 0; i < 8; i++)
                #pragma unroll
                for (int j = 0; j < 8; j++)
                    acc[i][j] = fmaf(ra[i], rb[j], acc[i][j]);
        }
        __syncthreads();
    }

    #pragma unroll
    for (int i = 0; i < 8; i++) {
        int row = brow + ty * 8 + i;
        const float* gp = (MODE == 2) ? (g_mod + (row >> 10) * 9216 + gOff) : nullptr;
        #pragma unroll
        for (int j = 0; j < 8; j++) {
            int col = bcol + tx * 8 + j;
            float v = acc[i][j] + bias[col];
            if (MODE == 1) {
                float z = v;
                float t = tanhf(0.7978845608028654f * (z + 0.044715f * z * z * z));
                v = 0.5f * z * (1.f + t);
            } else if (MODE == 2) {
                v = base[(size_t)row * N + col] + gp[col] * v;
            }
            C[(size_t)row * N + col] = v;
        }
    }
}

// ---------------- scores = Q @ K^T * 1/8 ; batch z = s*16+h ; cross -> K from seq s^1 ----
__global__ void scores_kernel(int cross) {
    int z = blockIdx.z, s = z >> 4, h = z & 15;
    int ks = cross ? (s ^ 1) : s;
    const float* Q  = g_qkv + (size_t)s  * 3145728 + h * 64;
    const float* Kp = g_qkv + (size_t)ks * 3145728 + 1024 + h * 64;
    float* C = g_scores + (size_t)z * 1048576;
    __shared__ float As[16][64];
    __shared__ float Bs[16][64];
    int t = threadIdx.x;
    int lr = t >> 2, lk = (t & 3) * 4;
    int ty = t >> 4, tx = t & 15;
    int i0 = blockIdx.y * 64, j0 = blockIdx.x * 64;
    float acc[4][4];
    #pragma unroll
    for (int i = 0; i < 4; i++)
        #pragma unroll
        for (int j = 0; j < 4; j++) acc[i][j] = 0.f;
    for (int k0 = 0; k0 < 64; k0 += 16) {
        float4 a = *(const float4*)(Q + (size_t)(i0 + lr) * 3072 + k0 + lk);
        As[lk][lr] = a.x; As[lk + 1][lr] = a.y; As[lk + 2][lr] = a.z; As[lk + 3][lr] = a.w;
        float4 b = *(const float4*)(Kp + (size_t)(j0 + lr) * 3072 + k0 + lk);
        Bs[lk][lr] = b.x; Bs[lk + 1][lr] = b.y; Bs[lk + 2][lr] = b.z; Bs[lk + 3][lr] = b.w;
        __syncthreads();
        #pragma unroll
        for (int k = 0; k < 16; k++) {
            float ra[4], rb[4];
            #pragma unroll
            for (int i = 0; i < 4; i++) ra[i] = As[k][ty * 4 + i];
            #pragma unroll
            for (int j = 0; j < 4; j++) rb[j] = Bs[k][tx * 4 + j];
            #pragma unroll
            for (int i = 0; i < 4; i++)
                #pragma unroll
                for (int j = 0; j < 4; j++)
                    acc[i][j] = fmaf(ra[i], rb[j], acc[i][j]);
        }
        __syncthreads();
    }
    #pragma unroll
    for (int i = 0; i < 4; i++)
        #pragma unroll
        for (int j = 0; j < 4; j++)
            C[(size_t)(i0 + ty * 4 + i) * 1024 + j0 + tx * 4 + j] = acc[i][j] * 0.125f;
}

// ---------------- row softmax over 1024 (one block per row) ----------------
__global__ void softmax_kernel() {
    size_t r = blockIdx.x;
    float4* row = (float4*)(g_scores + r * 1024);
    int t = threadIdx.x;
    float4 v = row[t];
    __shared__ float sm[8];
    float wm = warpMax(fmaxf(fmaxf(v.x, v.y), fmaxf(v.z, v.w)));
    if ((t & 31) == 0) sm[t >> 5] = wm;
    __syncthreads();
    float gm = sm[0];
    #pragma unroll
    for (int i = 1; i < 8; i++) gm = fmaxf(gm, sm[i]);
    __syncthreads();
    v.x = __expf(v.x - gm); v.y = __expf(v.y - gm);
    v.z = __expf(v.z - gm); v.w = __expf(v.w - gm);
    float ws = warpSum(v.x + v.y + v.z + v.w);
    if ((t & 31) == 0) sm[t >> 5] = ws;
    __syncthreads();
    float tot = 0.f;
    #pragma unroll
    for (int i = 0; i < 8; i++) tot += sm[i];
    float inv = 1.f / tot;
    v.x *= inv; v.y *= inv; v.z *= inv; v.w *= inv;
    row[t] = v;
}

// ---------------- O = P @ V, scatter to attnout[s, n, h*64+d] ; cross -> V from s^1 -----
__global__ void pv_kernel(int cross) {
    int z = blockIdx.z, s = z >> 4, h = z & 15;
    int vs = cross ? (s ^ 1) : s;
    const float* P = g_scores + (size_t)z * 1048576;
    const float* V = g_qkv + (size_t)vs * 3145728 + 2048 + h * 64;
    __shared__ float As[16][64];
    __shared__ float Bs[16][64];
    int t = threadIdx.x;
    int i0 = blockIdx.x * 64;
    int ty = t >> 4, tx = t & 15;
    int lr = t >> 2, lk = (t & 3) * 4;
    int vk = t >> 4, vj = (t & 15) * 4;
    float acc[4][4];
    #pragma unroll
    for (int i = 0; i < 4; i++)
        #pragma unroll
        for (int j = 0; j < 4; j++) acc[i][j] = 0.f;
    for (int k0 = 0; k0 < 1024; k0 += 16) {
        float4 a = *(const float4*)(P + (size_t)(i0 + lr) * 1024 + k0 + lk);
        As[lk][lr] = a.x; As[lk + 1][lr] = a.y; As[lk + 2][lr] = a.z; As[lk + 3][lr] = a.w;
        float4 b = *(const float4*)(V + (size_t)(k0 + vk) * 3072 + vj);
        *(float4*)&Bs[vk][vj] = b;
        __syncthreads();
        #pragma unroll
        for (int k = 0; k < 16; k++) {
            float ra[4], rb[4];
            #pragma unroll
            for (int i = 0; i < 4; i++) ra[i] = As[k][ty * 4 + i];
            #pragma unroll
            for (int j = 0; j < 4; j++) rb[j] = Bs[k][tx * 4 + j];
            #pragma unroll
            for (int i = 0; i < 4; i++)
                #pragma unroll
                for (int j = 0; j < 4; j++)
                    acc[i][j] = fmaf(ra[i], rb[j], acc[i][j]);
        }
        __syncthreads();
    }
    float* O = g_attnout + (size_t)s * 1048576 + h * 64;
    #pragma unroll
    for (int i = 0; i < 4; i++)
        #pragma unroll
        for (int j = 0; j < 4; j++)
            O[(size_t)(i0 + ty * 4 + i) * 1024 + tx * 4 + j] = acc[i][j];
}

// ---------------- orchestration ----------------
extern "C" void kernel_launch(void* const* d_in, const int* in_sizes, int n_in,
                              void* d_out, int out_size) {
    const float* x           = (const float*)d_in[0];
    const float* c           = (const float*)d_in[1];
    const float* attn_qkv_w  = (const float*)d_in[2];
    const float* attn_qkv_b  = (const float*)d_in[3];
    const float* attn_proj_w = (const float*)d_in[4];
    const float* attn_proj_b = (const float*)d_in[5];
    const float* crs_qkv_w   = (const float*)d_in[6];
    const float* crs_qkv_b   = (const float*)d_in[7];
    const float* crs_proj_w  = (const float*)d_in[8];
    const float* crs_proj_b  = (const float*)d_in[9];
    const float* mlp_fc1_w   = (const float*)d_in[10];
    const float* mlp_fc1_b   = (const float*)d_in[11];
    const float* mlp_fc2_w   = (const float*)d_in[12];
    const float* mlp_fc2_b   = (const float*)d_in[13];
    const float* ada_w       = (const float*)d_in[14];
    const float* ada_b       = (const float*)d_in[15];
    float* out = (float*)d_out;

    float *xln, *qkv, *attnout, *hbuf;
    cudaGetSymbolAddress((void**)&xln, g_xln);
    cudaGetSymbolAddress((void**)&qkv, g_qkv);
    cudaGetSymbolAddress((void**)&attnout, g_attnout);
    cudaGetSymbolAddress((void**)&hbuf, g_hbuf);

    // 1) adaLN modulation table
    mod_kernel<<<dim3(36, 4), 256>>>(c, ada_w, ada_b);

    // ---- self-attention (MSA): shOff=0, gate off=2048 ----
    // NOTE: MSA output feeds ONLY the cross-attention LN input (reference never
    // folds it into the residual stream). out = x + g_msa*msa temporarily.
    ln_mod_kernel<<<4096, 256>>>(x, xln, 0);
    sgemm128<0><<<dim3(24, 32), 256>>>(xln, attn_qkv_w, qkv, 1024, 3072, attn_qkv_b, nullptr, 0);
    scores_kernel<<<dim3(16, 16, 64), 256>>>(0);
    softmax_kernel<<<65536, 256>>>();
    pv_kernel<<<dim3(16, 1, 64), 256>>>(0);
    sgemm128<2><<<dim3(8, 32), 256>>>(attnout, attn_proj_w, out, 1024, 1024, attn_proj_b, x, 2048);

    // ---- cross-attention (MCA): shOff=3072, gate off=5120 ----
    // LN input = post-MSA state (out), but residual base = ORIGINAL x.
    ln_mod_kernel<<<4096, 256>>>(out, xln, 3072);
    sgemm128<0><<<dim3(24, 32), 256>>>(xln, crs_qkv_w, qkv, 1024, 3072, crs_qkv_b, nullptr, 0);
    scores_kernel<<<dim3(16, 16, 64), 256>>>(1);
    softmax_kernel<<<65536, 256>>>();
    pv_kernel<<<dim3(16, 1, 64), 256>>>(1);
    sgemm128<2><<<dim3(8, 32), 256>>>(attnout, crs_proj_w, out, 1024, 1024, crs_proj_b, x, 5120);

    // ---- MLP: shOff=6144, gate off=8192 ----
    ln_mod_kernel<<<4096, 256>>>(out, xln, 6144);
    sgemm128<1><<<dim3(32, 32), 256>>>(xln, mlp_fc1_w, hbuf, 1024, 4096, mlp_fc1_b, nullptr, 0);
    sgemm128<2><<<dim3(8, 32), 256>>>(hbuf, mlp_fc2_w, out, 4096, 1024, mlp_fc2_b, out, 8192);
}

// round 6
// speedup vs baseline: 2.5739x; 2.5739x over previous
#include <cuda_runtime.h>
#include <cuda_fp16.h>
#include <math.h>
#include <stdint.h>

// ---------------- scratch (static device globals: allocation-free) ----------------
__device__ float  g_mod[4 * 9216];                  // (b,half) x 9*1024
__device__ float  g_qkv[4096 * 3072];               // qkv projections (fp32 for attention)
__device__ float  g_scores[67108864];               // 64 x 1024 x 1024 attention probs
__device__ __half g_xln_h[4096 * 1024];             // LN+mod output (half, GEMM A)
__device__ __half g_attnout_h[4096 * 1024];         // attention output (half, GEMM A)
__device__ __half g_hbuf_h[4096 * 4096];            // MLP hidden (half, GEMM A)
__device__ __half g_wt[16777216];                   // transposed half weights [N,K]

#define WT_ATTN_QKV  0
#define WT_CRS_QKV   3145728
#define WT_ATTN_PROJ 6291456
#define WT_CRS_PROJ  7340032
#define WT_FC1       8388608
#define WT_FC2       12582912

__device__ __forceinline__ uint32_t smem_to_u32(const void* p) {
    uint32_t a;
    asm("{ .reg .u64 t; cvta.to.shared.u64 t, %1; cvt.u32.u64 %0, t; }" : "=r"(a) : "l"(p));
    return a;
}

// ---------------- reduction helpers ----------------
__device__ __forceinline__ float warpSum(float v) {
    #pragma unroll
    for (int o = 16; o > 0; o >>= 1) v += __shfl_xor_sync(0xffffffffu, v, o);
    return v;
}
__device__ __forceinline__ float warpMax(float v) {
    #pragma unroll
    for (int o = 16; o > 0; o >>= 1) v = fmaxf(v, __shfl_xor_sync(0xffffffffu, v, o));
    return v;
}

// ---------------- weight transpose + fp16 convert: Wt[n][k] = (half)W[k][n] ----------------
__global__ void transpose_cvt(const float* __restrict__ W, __half* __restrict__ Wt, int K, int N) {
    __shared__ float tile[32][33];
    int n0 = blockIdx.x * 32, k0 = blockIdx.y * 32;
    int tx = threadIdx.x, ty = threadIdx.y;   // (32,8)
    #pragma unroll
    for (int i = 0; i < 4; i++)
        tile[ty * 4 + i][tx] = W[(size_t)(k0 + ty * 4 + i) * N + n0 + tx];
    __syncthreads();
    #pragma unroll
    for (int i = 0; i < 4; i++)
        Wt[(size_t)(n0 + ty * 4 + i) * K + k0 + tx] = __float2half_rn(tile[tx][ty * 4 + i]);
}

// ---------------- adaLN modulation ----------------
__global__ void mod_kernel(const float* __restrict__ c,
                           const float* __restrict__ ada_w,
                           const float* __restrict__ ada_b) {
    __shared__ float sc[1024];
    int bj = blockIdx.y;
    int o  = blockIdx.x * 256 + threadIdx.x;
    const float* crow = c + bj * 1024;
    for (int i = threadIdx.x; i < 1024; i += 256) {
        float v = crow[i];
        sc[i] = v / (1.f + __expf(-v));
    }
    __syncthreads();
    float acc = 0.f;
    #pragma unroll 4
    for (int k = 0; k < 1024; k++)
        acc = fmaf(sc[k], ada_w[(size_t)k * 9216 + o], acc);
    g_mod[bj * 9216 + o] = acc + ada_b[o];
}

// ---------------- fused LayerNorm + modulation -> half ----------------
__global__ void ln_mod_kernel(const float* __restrict__ x, __half* __restrict__ y, int shOff) {
    int r = blockIdx.x;
    int s = r >> 10;
    int t = threadIdx.x;
    const float4* xr = (const float4*)(x + (size_t)r * 1024);
    float4 v = xr[t];
    __shared__ float sm[8];
    float ws = warpSum(v.x + v.y + v.z + v.w);
    if ((t & 31) == 0) sm[t >> 5] = ws;
    __syncthreads();
    float mu;
    { float s8 = 0.f;
      #pragma unroll
      for (int i = 0; i < 8; i++) s8 += sm[i];
      mu = s8 * (1.f / 1024.f); }
    __syncthreads();
    float dx = v.x - mu, dy = v.y - mu, dz = v.z - mu, dw = v.w - mu;
    float wv = warpSum(dx * dx + dy * dy + dz * dz + dw * dw);
    if ((t & 31) == 0) sm[t >> 5] = wv;
    __syncthreads();
    float var;
    { float s8 = 0.f;
      #pragma unroll
      for (int i = 0; i < 8; i++) s8 += sm[i];
      var = s8 * (1.f / 1024.f); }
    float inv = rsqrtf(var + 1e-6f);
    const float* m = g_mod + s * 9216 + shOff;
    float4 shv = *(const float4*)(m + t * 4);
    float4 scv = *(const float4*)(m + 1024 + t * 4);
    float ox = dx * inv * (1.f + scv.x) + shv.x;
    float oy = dy * inv * (1.f + scv.y) + shv.y;
    float oz = dz * inv * (1.f + scv.z) + shv.z;
    float ow = dw * inv * (1.f + scv.w) + shv.w;
    __half2* yr = (__half2*)(y + (size_t)r * 1024);
    yr[t * 2 + 0] = __floats2half2_rn(ox, oy);
    yr[t * 2 + 1] = __floats2half2_rn(oz, ow);
}

// ---------------- warp-MMA fp16 GEMM: C(MxN) = A(MxK) @ Bt(NxK)^T ----------------
// mma.sync.m16n8k16 (HMMA), 128x128 CTA tile, 8 warps of 64x32, K-chunk 64.
// MODE 0: C = acc + bias                              (fp32 out)
// MODE 1: C = gelu_tanh(acc + bias)                   (half out)
// MODE 2: C = base + gate[(row>>10)*9216+gOff+col]*(acc+bias)   (fp32 out)
#define LDMX4(r0, r1, r2, r3, addr) \
    asm volatile("ldmatrix.sync.aligned.m8n8.x4.shared.b16 {%0,%1,%2,%3}, [%4];" \
                 : "=r"(r0), "=r"(r1), "=r"(r2), "=r"(r3) : "r"(addr))
#define MMA16816(d, a, b0v, b1v) \
    asm volatile("mma.sync.aligned.m16n8k16.row.col.f32.f16.f16.f32 " \
                 "{%0,%1,%2,%3}, {%4,%5,%6,%7}, {%8,%9}, {%0,%1,%2,%3};" \
                 : "+f"((d)[0]), "+f"((d)[1]), "+f"((d)[2]), "+f"((d)[3]) \
                 : "r"((a)[0]), "r"((a)[1]), "r"((a)[2]), "r"((a)[3]), "r"(b0v), "r"(b1v))

template <int MODE, int OUTHALF>
__global__ void __launch_bounds__(256)
hgemm(const __half* __restrict__ A, const __half* __restrict__ Bt,
      void* __restrict__ Cv, int K, int N,
      const float* __restrict__ bias,
      const float* __restrict__ base, int gOff) {
    __shared__ __half As[128][72];
    __shared__ __half Bs[128][72];
    int tid = threadIdx.x;
    int wid = tid >> 5, lane = tid & 31;
    int brow = blockIdx.y * 128, bcol = blockIdx.x * 128;
    int wr = wid & 1, wc = wid >> 1;           // warp tile: rows wr*64, cols wc*32

    uint32_t asb = smem_to_u32(As);
    uint32_t bsb = smem_to_u32(Bs);
    // ldmatrix lane address components (shared by A and B patterns)
    int lrow = lane & 15, lkb = (lane >> 4) * 8;

    float acc[4][4][4];
    #pragma unroll
    for (int i = 0; i < 4; i++)
        #pragma unroll
        for (int j = 0; j < 4; j++)
            #pragma unroll
            for (int q = 0; q < 4; q++) acc[i][j][q] = 0.f;

    int ldr = tid >> 3, ldg = (tid & 7) * 8;   // smem store: row, col-group

    for (int k0 = 0; k0 < K; k0 += 64) {
        #pragma unroll
        for (int i = 0; i < 4; i++) {
            int r = ldr + i * 32;
            *(uint4*)&As[r][ldg] = *(const uint4*)(A  + (size_t)(brow + r) * K + k0 + ldg);
            *(uint4*)&Bs[r][ldg] = *(const uint4*)(Bt + (size_t)(bcol + r) * K + k0 + ldg);
        }
        __syncthreads();
        #pragma unroll
        for (int kk = 0; kk < 4; kk++) {
            uint32_t a[4][4], b[2][4];
            #pragma unroll
            for (int mt = 0; mt < 4; mt++) {
                uint32_t addr = asb + ((wr * 64 + mt * 16 + lrow) * 72 + kk * 16 + lkb) * 2;
                LDMX4(a[mt][0], a[mt][1], a[mt][2], a[mt][3], addr);
            }
            #pragma unroll
            for (int ng = 0; ng < 2; ng++) {
                uint32_t addr = bsb + ((wc * 32 + ng * 16 + lrow) * 72 + kk * 16 + lkb) * 2;
                LDMX4(b[ng][0], b[ng][1], b[ng][2], b[ng][3], addr);
            }
            #pragma unroll
            for (int mt = 0; mt < 4; mt++)
                #pragma unroll
                for (int j = 0; j < 4; j++)
                    MMA16816(acc[mt][j], a[mt], b[j >> 1][j & 1], b[j >> 1][(j & 1) + 2]);
        }
        __syncthreads();
    }

    // ---- epilogue ----
    int cbase = bcol + wc * 32;
    #pragma unroll
    for (int mt = 0; mt < 4; mt++) {
        int r0 = brow + wr * 64 + mt * 16 + (lane >> 2);
        #pragma unroll
        for (int half_ = 0; half_ < 2; half_++) {
            int row = r0 + half_ * 8;
            const float* gp = (MODE == 2) ? (g_mod + (row >> 10) * 9216 + gOff) : nullptr;
            #pragma unroll
            for (int j = 0; j < 4; j++) {
                int col = cbase + j * 8 + (lane & 3) * 2;
                float v0 = acc[mt][j][half_ * 2 + 0] + bias[col];
                float v1 = acc[mt][j][half_ * 2 + 1] + bias[col + 1];
                if (MODE == 1) {
                    float u0 = 0.7978845608028654f * (v0 + 0.044715f * v0 * v0 * v0);
                    float u1 = 0.7978845608028654f * (v1 + 0.044715f * v1 * v1 * v1);
                    v0 = __fdividef(v0, 1.f + __expf(-2.f * u0));
                    v1 = __fdividef(v1, 1.f + __expf(-2.f * u1));
                } else if (MODE == 2) {
                    const float* basep = base + (size_t)row * N + col;
                    v0 = basep[0] + gp[col] * v0;
                    v1 = basep[1] + gp[col + 1] * v1;
                }
                if (OUTHALF) {
                    *(__half2*)((__half*)Cv + (size_t)row * N + col) = __floats2half2_rn(v0, v1);
                } else {
                    *(float2*)((float*)Cv + (size_t)row * N + col) = make_float2(v0, v1);
                }
            }
        }
    }
}

// ---------------- scores = Q @ K^T * 1/8 ----------------
__global__ void scores_kernel(int cross) {
    int z = blockIdx.z, s = z >> 4, h = z & 15;
    int ks = cross ? (s ^ 1) : s;
    const float* Q  = g_qkv + (size_t)s  * 3145728 + h * 64;
    const float* Kp = g_qkv + (size_t)ks * 3145728 + 1024 + h * 64;
    float* C = g_scores + (size_t)z * 1048576;
    __shared__ float As[16][64];
    __shared__ float Bs[16][64];
    int t = threadIdx.x;
    int lr = t >> 2, lk = (t & 3) * 4;
    int ty = t >> 4, tx = t & 15;
    int i0 = blockIdx.y * 64, j0 = blockIdx.x * 64;
    float acc[4][4];
    #pragma unroll
    for (int i = 0; i < 4; i++)
        #pragma unroll
        for (int j = 0; j < 4; j++) acc[i][j] = 0.f;
    for (int k0 = 0; k0 < 64; k0 += 16) {
        float4 a = *(const float4*)(Q + (size_t)(i0 + lr) * 3072 + k0 + lk);
        As[lk][lr] = a.x; As[lk + 1][lr] = a.y; As[lk + 2][lr] = a.z; As[lk + 3][lr] = a.w;
        float4 b = *(const float4*)(Kp + (size_t)(j0 + lr) * 3072 + k0 + lk);
        Bs[lk][lr] = b.x; Bs[lk + 1][lr] = b.y; Bs[lk + 2][lr] = b.z; Bs[lk + 3][lr] = b.w;
        __syncthreads();
        #pragma unroll
        for (int k = 0; k < 16; k++) {
            float ra[4], rb[4];
            #pragma unroll
            for (int i = 0; i < 4; i++) ra[i] = As[k][ty * 4 + i];
            #pragma unroll
            for (int j = 0; j < 4; j++) rb[j] = Bs[k][tx * 4 + j];
            #pragma unroll
            for (int i = 0; i < 4; i++)
                #pragma unroll
                for (int j = 0; j < 4; j++)
                    acc[i][j] = fmaf(ra[i], rb[j], acc[i][j]);
        }
        __syncthreads();
    }
    #pragma unroll
    for (int i = 0; i < 4; i++)
        #pragma unroll
        for (int j = 0; j < 4; j++)
            C[(size_t)(i0 + ty * 4 + i) * 1024 + j0 + tx * 4 + j] = acc[i][j] * 0.125f;
}

// ---------------- row softmax over 1024 ----------------
__global__ void softmax_kernel() {
    size_t r = blockIdx.x;
    float4* row = (float4*)(g_scores + r * 1024);
    int t = threadIdx.x;
    float4 v = row[t];
    __shared__ float sm[8];
    float wm = warpMax(fmaxf(fmaxf(v.x, v.y), fmaxf(v.z, v.w)));
    if ((t & 31) == 0) sm[t >> 5] = wm;
    __syncthreads();
    float gm = sm[0];
    #pragma unroll
    for (int i = 1; i < 8; i++) gm = fmaxf(gm, sm[i]);
    __syncthreads();
    v.x = __expf(v.x - gm); v.y = __expf(v.y - gm);
    v.z = __expf(v.z - gm); v.w = __expf(v.w - gm);
    float ws = warpSum(v.x + v.y + v.z + v.w);
    if ((t & 31) == 0) sm[t >> 5] = ws;
    __syncthreads();
    float tot = 0.f;
    #pragma unroll
    for (int i = 0; i < 8; i++) tot += sm[i];
    float inv = 1.f / tot;
    v.x *= inv; v.y *= inv; v.z *= inv; v.w *= inv;
    row[t] = v;
}

// ---------------- O = P @ V -> half attnout ----------------
__global__ void pv_kernel(int cross) {
    int z = blockIdx.z, s = z >> 4, h = z & 15;
    int vs = cross ? (s ^ 1) : s;
    const float* P = g_scores + (size_t)z * 1048576;
    const float* V = g_qkv + (size_t)vs * 3145728 + 2048 + h * 64;
    __shared__ float As[16][64];
    __shared__ float Bs[16][64];
    int t = threadIdx.x;
    int i0 = blockIdx.x * 64;
    int ty = t >> 4, tx = t & 15;
    int lr = t >> 2, lk = (t & 3) * 4;
    int vk = t >> 4, vj = (t & 15) * 4;
    float acc[4][4];
    #pragma unroll
    for (int i = 0; i < 4; i++)
        #pragma unroll
        for (int j = 0; j < 4; j++) acc[i][j] = 0.f;
    for (int k0 = 0; k0 < 1024; k0 += 16) {
        float4 a = *(const float4*)(P + (size_t)(i0 + lr) * 1024 + k0 + lk);
        As[lk][lr] = a.x; As[lk + 1][lr] = a.y; As[lk + 2][lr] = a.z; As[lk + 3][lr] = a.w;
        float4 b = *(const float4*)(V + (size_t)(k0 + vk) * 3072 + vj);
        *(float4*)&Bs[vk][vj] = b;
        __syncthreads();
        #pragma unroll
        for (int k = 0; k < 16; k++) {
            float ra[4], rb[4];
            #pragma unroll
            for (int i = 0; i < 4; i++) ra[i] = As[k][ty * 4 + i];
            #pragma unroll
            for (int j = 0; j < 4; j++) rb[j] = Bs[k][tx * 4 + j];
            #pragma unroll
            for (int i = 0; i < 4; i++)
                #pragma unroll
                for (int j = 0; j < 4; j++)
                    acc[i][j] = fmaf(ra[i], rb[j], acc[i][j]);
        }
        __syncthreads();
    }
    __half* O = g_attnout_h + (size_t)s * 1048576 + h * 64;
    #pragma unroll
    for (int i = 0; i < 4; i++)
        #pragma unroll
        for (int j = 0; j < 4; j++)
            O[(size_t)(i0 + ty * 4 + i) * 1024 + tx * 4 + j] = __float2half_rn(acc[i][j]);
}

// ---------------- orchestration ----------------
extern "C" void kernel_launch(void* const* d_in, const int* in_sizes, int n_in,
                              void* d_out, int out_size) {
    const float* x           = (const float*)d_in[0];
    const float* c           = (const float*)d_in[1];
    const float* attn_qkv_w  = (const float*)d_in[2];
    const float* attn_qkv_b  = (const float*)d_in[3];
    const float* attn_proj_w = (const float*)d_in[4];
    const float* attn_proj_b = (const float*)d_in[5];
    const float* crs_qkv_w   = (const float*)d_in[6];
    const float* crs_qkv_b   = (const float*)d_in[7];
    const float* crs_proj_w  = (const float*)d_in[8];
    const float* crs_proj_b  = (const float*)d_in[9];
    const float* mlp_fc1_w   = (const float*)d_in[10];
    const float* mlp_fc1_b   = (const float*)d_in[11];
    const float* mlp_fc2_w   = (const float*)d_in[12];
    const float* mlp_fc2_b   = (const float*)d_in[13];
    const float* ada_w       = (const float*)d_in[14];
    const float* ada_b       = (const float*)d_in[15];
    float* out = (float*)d_out;

    float *qkv;
    __half *xln, *attnout, *hbuf, *wt;
    cudaGetSymbolAddress((void**)&qkv, g_qkv);
    cudaGetSymbolAddress((void**)&xln, g_xln_h);
    cudaGetSymbolAddress((void**)&attnout, g_attnout_h);
    cudaGetSymbolAddress((void**)&hbuf, g_hbuf_h);
    cudaGetSymbolAddress((void**)&wt, g_wt);

    dim3 tb(32, 8);
    transpose_cvt<<<dim3(96, 32),  tb>>>(attn_qkv_w,  wt + WT_ATTN_QKV,  1024, 3072);
    transpose_cvt<<<dim3(96, 32),  tb>>>(crs_qkv_w,   wt + WT_CRS_QKV,   1024, 3072);
    transpose_cvt<<<dim3(32, 32),  tb>>>(attn_proj_w, wt + WT_ATTN_PROJ, 1024, 1024);
    transpose_cvt<<<dim3(32, 32),  tb>>>(crs_proj_w,  wt + WT_CRS_PROJ,  1024, 1024);
    transpose_cvt<<<dim3(128, 32), tb>>>(mlp_fc1_w,   wt + WT_FC1,       1024, 4096);
    transpose_cvt<<<dim3(32, 128), tb>>>(mlp_fc2_w,   wt + WT_FC2,       4096, 1024);

    mod_kernel<<<dim3(36, 4), 256>>>(c, ada_w, ada_b);

    // ---- self-attention (MSA): shOff=0, gate off=2048 ----
    ln_mod_kernel<<<4096, 256>>>(x, xln, 0);
    hgemm<0, 0><<<dim3(24, 32), 256>>>(xln, wt + WT_ATTN_QKV, qkv, 1024, 3072,
                                       attn_qkv_b, nullptr, 0);
    scores_kernel<<<dim3(16, 16, 64), 256>>>(0);
    softmax_kernel<<<65536, 256>>>();
    pv_kernel<<<dim3(16, 1, 64), 256>>>(0);
    hgemm<2, 0><<<dim3(8, 32), 256>>>(attnout, wt + WT_ATTN_PROJ, out, 1024, 1024,
                                      attn_proj_b, x, 2048);

    // ---- cross-attention (MCA): LN reads post-MSA, residual base = original x ----
    ln_mod_kernel<<<4096, 256>>>(out, xln, 3072);
    hgemm<0, 0><<<dim3(24, 32), 256>>>(xln, wt + WT_CRS_QKV, qkv, 1024, 3072,
                                       crs_qkv_b, nullptr, 0);
    scores_kernel<<<dim3(16, 16, 64), 256>>>(1);
    softmax_kernel<<<65536, 256>>>();
    pv_kernel<<<dim3(16, 1, 64), 256>>>(1);
    hgemm<2, 0><<<dim3(8, 32), 256>>>(attnout, wt + WT_CRS_PROJ, out, 1024, 1024,
                                      crs_proj_b, x, 5120);

    // ---- MLP: shOff=6144, gate off=8192 ----
    ln_mod_kernel<<<4096, 256>>>(out, xln, 6144);
    hgemm<1, 1><<<dim3(32, 32), 256>>>(xln, wt + WT_FC1, hbuf, 1024, 4096,
                                       mlp_fc1_b, nullptr, 0);
    hgemm<2, 0><<<dim3(8, 32), 256>>>(hbuf, wt + WT_FC2, out, 4096, 1024,
                                      mlp_fc2_b, out, 8192);
}

// round 7
// speedup vs baseline: 5.6238x; 2.1849x over previous
#include <cuda_runtime.h>
#include <cuda_fp16.h>
#include <math.h>
#include <stdint.h>

// ---------------- scratch (static device globals: allocation-free) ----------------
__device__ float  g_mod[4 * 9216];                  // (b,half) x 9*1024
__device__ __half g_qkv_h[4096 * 3072];             // qkv projections (half)
__device__ __half g_xln_h[4096 * 1024];             // LN+mod output (half, GEMM A)
__device__ __half g_attnout_h[4096 * 1024];         // attention output (half, GEMM A)
__device__ __half g_hbuf_h[4096 * 4096];            // MLP hidden (half, GEMM A)
__device__ __half g_wt[16777216];                   // transposed half weights [N,K]

#define WT_ATTN_QKV  0
#define WT_CRS_QKV   3145728
#define WT_ATTN_PROJ 6291456
#define WT_CRS_PROJ  7340032
#define WT_FC1       8388608
#define WT_FC2       12582912

__device__ __forceinline__ uint32_t smem_to_u32(const void* p) {
    uint32_t a;
    asm("{ .reg .u64 t; cvta.to.shared.u64 t, %1; cvt.u32.u64 %0, t; }" : "=r"(a) : "l"(p));
    return a;
}
__device__ __forceinline__ uint32_t packh2(float a, float b) {
    __half2 h = __floats2half2_rn(a, b);
    return *(uint32_t*)&h;
}

// ---------------- reduction helpers ----------------
__device__ __forceinline__ float warpSum(float v) {
    #pragma unroll
    for (int o = 16; o > 0; o >>= 1) v += __shfl_xor_sync(0xffffffffu, v, o);
    return v;
}
__device__ __forceinline__ float warpMax(float v) {
    #pragma unroll
    for (int o = 16; o > 0; o >>= 1) v = fmaxf(v, __shfl_xor_sync(0xffffffffu, v, o));
    return v;
}
// reduce across the 4 lanes sharing one C-fragment row
__device__ __forceinline__ float quadMax(float v) {
    v = fmaxf(v, __shfl_xor_sync(0xffffffffu, v, 1));
    v = fmaxf(v, __shfl_xor_sync(0xffffffffu, v, 2));
    return v;
}
__device__ __forceinline__ float quadSum(float v) {
    v += __shfl_xor_sync(0xffffffffu, v, 1);
    v += __shfl_xor_sync(0xffffffffu, v, 2);
    return v;
}

// ---------------- mma / ldmatrix macros ----------------
#define LDMX4(r0, r1, r2, r3, addr) \
    asm volatile("ldmatrix.sync.aligned.m8n8.x4.shared.b16 {%0,%1,%2,%3}, [%4];" \
                 : "=r"(r0), "=r"(r1), "=r"(r2), "=r"(r3) : "r"(addr))
#define LDMX4T(r0, r1, r2, r3, addr) \
    asm volatile("ldmatrix.sync.aligned.m8n8.x4.trans.shared.b16 {%0,%1,%2,%3}, [%4];" \
                 : "=r"(r0), "=r"(r1), "=r"(r2), "=r"(r3) : "r"(addr))
#define MMA16816(d, a, b0v, b1v) \
    asm volatile("mma.sync.aligned.m16n8k16.row.col.f32.f16.f16.f32 " \
                 "{%0,%1,%2,%3}, {%4,%5,%6,%7}, {%8,%9}, {%0,%1,%2,%3};" \
                 : "+f"((d)[0]), "+f"((d)[1]), "+f"((d)[2]), "+f"((d)[3]) \
                 : "r"((a)[0]), "r"((a)[1]), "r"((a)[2]), "r"((a)[3]), "r"(b0v), "r"(b1v))

// ---------------- weight transpose + fp16 convert: Wt[n][k] = (half)W[k][n] ----------------
__global__ void transpose_cvt(const float* __restrict__ W, __half* __restrict__ Wt, int K, int N) {
    __shared__ float tile[32][33];
    int n0 = blockIdx.x * 32, k0 = blockIdx.y * 32;
    int tx = threadIdx.x, ty = threadIdx.y;   // (32,8)
    #pragma unroll
    for (int i = 0; i < 4; i++)
        tile[ty * 4 + i][tx] = W[(size_t)(k0 + ty * 4 + i) * N + n0 + tx];
    __syncthreads();
    #pragma unroll
    for (int i = 0; i < 4; i++)
        Wt[(size_t)(n0 + ty * 4 + i) * K + k0 + tx] = __float2half_rn(tile[tx][ty * 4 + i]);
}

// ---------------- adaLN modulation ----------------
__global__ void mod_kernel(const float* __restrict__ c,
                           const float* __restrict__ ada_w,
                           const float* __restrict__ ada_b) {
    __shared__ float sc[1024];
    int bj = blockIdx.y;
    int o  = blockIdx.x * 256 + threadIdx.x;
    const float* crow = c + bj * 1024;
    for (int i = threadIdx.x; i < 1024; i += 256) {
        float v = crow[i];
        sc[i] = v / (1.f + __expf(-v));
    }
    __syncthreads();
    float acc = 0.f;
    #pragma unroll 4
    for (int k = 0; k < 1024; k++)
        acc = fmaf(sc[k], ada_w[(size_t)k * 9216 + o], acc);
    g_mod[bj * 9216 + o] = acc + ada_b[o];
}

// ---------------- fused LayerNorm + modulation -> half ----------------
__global__ void ln_mod_kernel(const float* __restrict__ x, __half* __restrict__ y, int shOff) {
    int r = blockIdx.x;
    int s = r >> 10;
    int t = threadIdx.x;
    const float4* xr = (const float4*)(x + (size_t)r * 1024);
    float4 v = xr[t];
    __shared__ float sm[8];
    float ws = warpSum(v.x + v.y + v.z + v.w);
    if ((t & 31) == 0) sm[t >> 5] = ws;
    __syncthreads();
    float mu;
    { float s8 = 0.f;
      #pragma unroll
      for (int i = 0; i < 8; i++) s8 += sm[i];
      mu = s8 * (1.f / 1024.f); }
    __syncthreads();
    float dx = v.x - mu, dy = v.y - mu, dz = v.z - mu, dw = v.w - mu;
    float wv = warpSum(dx * dx + dy * dy + dz * dz + dw * dw);
    if ((t & 31) == 0) sm[t >> 5] = wv;
    __syncthreads();
    float var;
    { float s8 = 0.f;
      #pragma unroll
      for (int i = 0; i < 8; i++) s8 += sm[i];
      var = s8 * (1.f / 1024.f); }
    float inv = rsqrtf(var + 1e-6f);
    const float* m = g_mod + s * 9216 + shOff;
    float4 shv = *(const float4*)(m + t * 4);
    float4 scv = *(const float4*)(m + 1024 + t * 4);
    float ox = dx * inv * (1.f + scv.x) + shv.x;
    float oy = dy * inv * (1.f + scv.y) + shv.y;
    float oz = dz * inv * (1.f + scv.z) + shv.z;
    float ow = dw * inv * (1.f + scv.w) + shv.w;
    __half2* yr = (__half2*)(y + (size_t)r * 1024);
    yr[t * 2 + 0] = __floats2half2_rn(ox, oy);
    yr[t * 2 + 1] = __floats2half2_rn(oz, ow);
}

// ---------------- warp-MMA fp16 GEMM: C(MxN) = A(MxK) @ Bt(NxK)^T ----------------
// MODE 0: C = acc + bias ; MODE 1: gelu(acc+bias) ; MODE 2: base + gate*(acc+bias)
template <int MODE, int OUTHALF>
__global__ void __launch_bounds__(256)
hgemm(const __half* __restrict__ A, const __half* __restrict__ Bt,
      void* __restrict__ Cv, int K, int N,
      const float* __restrict__ bias,
      const float* __restrict__ base, int gOff) {
    __shared__ __half As[128][72];
    __shared__ __half Bs[128][72];
    int tid = threadIdx.x;
    int wid = tid >> 5, lane = tid & 31;
    int brow = blockIdx.y * 128, bcol = blockIdx.x * 128;
    int wr = wid & 1, wc = wid >> 1;

    uint32_t asb = smem_to_u32(As);
    uint32_t bsb = smem_to_u32(Bs);
    int lrow = lane & 15, lkb = (lane >> 4) * 8;

    float acc[4][4][4];
    #pragma unroll
    for (int i = 0; i < 4; i++)
        #pragma unroll
        for (int j = 0; j < 4; j++)
            #pragma unroll
            for (int q = 0; q < 4; q++) acc[i][j][q] = 0.f;

    int ldr = tid >> 3, ldg = (tid & 7) * 8;

    for (int k0 = 0; k0 < K; k0 += 64) {
        #pragma unroll
        for (int i = 0; i < 4; i++) {
            int r = ldr + i * 32;
            *(uint4*)&As[r][ldg] = *(const uint4*)(A  + (size_t)(brow + r) * K + k0 + ldg);
            *(uint4*)&Bs[r][ldg] = *(const uint4*)(Bt + (size_t)(bcol + r) * K + k0 + ldg);
        }
        __syncthreads();
        #pragma unroll
        for (int kk = 0; kk < 4; kk++) {
            uint32_t a[4][4], b[2][4];
            #pragma unroll
            for (int mt = 0; mt < 4; mt++) {
                uint32_t addr = asb + ((wr * 64 + mt * 16 + lrow) * 72 + kk * 16 + lkb) * 2;
                LDMX4(a[mt][0], a[mt][1], a[mt][2], a[mt][3], addr);
            }
            #pragma unroll
            for (int ng = 0; ng < 2; ng++) {
                uint32_t addr = bsb + ((wc * 32 + ng * 16 + lrow) * 72 + kk * 16 + lkb) * 2;
                LDMX4(b[ng][0], b[ng][1], b[ng][2], b[ng][3], addr);
            }
            #pragma unroll
            for (int mt = 0; mt < 4; mt++)
                #pragma unroll
                for (int j = 0; j < 4; j++)
                    MMA16816(acc[mt][j], a[mt], b[j >> 1][j & 1], b[j >> 1][(j & 1) + 2]);
        }
        __syncthreads();
    }

    int cbase = bcol + wc * 32;
    #pragma unroll
    for (int mt = 0; mt < 4; mt++) {
        int r0 = brow + wr * 64 + mt * 16 + (lane >> 2);
        #pragma unroll
        for (int half_ = 0; half_ < 2; half_++) {
            int row = r0 + half_ * 8;
            const float* gp = (MODE == 2) ? (g_mod + (row >> 10) * 9216 + gOff) : nullptr;
            #pragma unroll
            for (int j = 0; j < 4; j++) {
                int col = cbase + j * 8 + (lane & 3) * 2;
                float v0 = acc[mt][j][half_ * 2 + 0] + bias[col];
                float v1 = acc[mt][j][half_ * 2 + 1] + bias[col + 1];
                if (MODE == 1) {
                    float u0 = 0.7978845608028654f * (v0 + 0.044715f * v0 * v0 * v0);
                    float u1 = 0.7978845608028654f * (v1 + 0.044715f * v1 * v1 * v1);
                    v0 = __fdividef(v0, 1.f + __expf(-2.f * u0));
                    v1 = __fdividef(v1, 1.f + __expf(-2.f * u1));
                } else if (MODE == 2) {
                    const float* basep = base + (size_t)row * N + col;
                    v0 = basep[0] + gp[col] * v0;
                    v1 = basep[1] + gp[col + 1] * v1;
                }
                if (OUTHALF) {
                    *(__half2*)((__half*)Cv + (size_t)row * N + col) = __floats2half2_rn(v0, v1);
                } else {
                    *(float2*)((float*)Cv + (size_t)row * N + col) = make_float2(v0, v1);
                }
            }
        }
    }
}

// ---------------- fused flash attention (HMMA, online softmax) ----------------
// grid = (8 q-blocks, 64 zh). CTA: 8 warps x 16 query rows. Keys in 16 chunks of 64.
__global__ void __launch_bounds__(256)
flash_attn(int cross) {
    __shared__ __half Qs[128][72];
    __shared__ __half Ks[64][72];
    __shared__ __half Vs[64][72];

    int zh = blockIdx.y, s = zh >> 4, h = zh & 15;
    int ks = cross ? (s ^ 1) : s;
    int q0 = blockIdx.x * 128;
    int tid = threadIdx.x, wid = tid >> 5, lane = tid & 31;
    int lrow = lane & 15, lkb = (lane >> 4) * 8;
    int wq0 = wid * 16;

    uint32_t qsb = smem_to_u32(Qs);
    uint32_t ksb = smem_to_u32(Ks);
    uint32_t vsb = smem_to_u32(Vs);

    // load Q tile (128 x 64 half)
    {
        int ldr = tid >> 1, ldg = (tid & 1) * 32;   // 2 uint4 groups per row? 64 halves = 8 uint4
        // simpler: 1024 uint4 total, 4 per thread
        #pragma unroll
        for (int i = 0; i < 4; i++) {
            int idx = i * 256 + tid;
            int r = idx >> 3, g = (idx & 7) * 8;
            *(uint4*)&Qs[r][g] =
                *(const uint4*)(g_qkv_h + (size_t)(s * 1024 + q0 + r) * 3072 + h * 64 + g);
        }
        (void)ldr; (void)ldg;
    }
    __syncthreads();

    // Q fragments: 4 k-steps x 4 regs
    uint32_t qa[4][4];
    #pragma unroll
    for (int kk = 0; kk < 4; kk++) {
        uint32_t addr = qsb + ((wq0 + lrow) * 72 + kk * 16 + lkb) * 2;
        LDMX4(qa[kk][0], qa[kk][1], qa[kk][2], qa[kk][3], addr);
    }
    __syncthreads();   // Qs no longer needed as smem (frags held); reuse barrier for K/V below

    float O[8][4];
    #pragma unroll
    for (int j = 0; j < 8; j++)
        #pragma unroll
        for (int q = 0; q < 4; q++) O[j][q] = 0.f;
    float m0 = -1e30f, m1 = -1e30f, l0 = 0.f, l1 = 0.f;

    for (int c = 0; c < 16; c++) {
        int k0 = c * 64;
        #pragma unroll
        for (int i = 0; i < 2; i++) {
            int idx = i * 256 + tid;
            int r = idx >> 3, g = (idx & 7) * 8;
            const __half* src = g_qkv_h + (size_t)(ks * 1024 + k0 + r) * 3072 + h * 64 + g;
            *(uint4*)&Ks[r][g] = *(const uint4*)(src + 1024);
            *(uint4*)&Vs[r][g] = *(const uint4*)(src + 2048);
        }
        __syncthreads();

        // S = Q @ K^T (m16 x n64), fp32
        float S[8][4];
        #pragma unroll
        for (int j = 0; j < 8; j++)
            #pragma unroll
            for (int q = 0; q < 4; q++) S[j][q] = 0.f;
        #pragma unroll
        for (int kk = 0; kk < 4; kk++) {
            #pragma unroll
            for (int kg = 0; kg < 4; kg++) {           // key groups of 16
                uint32_t b0, b1, b2, b3;
                uint32_t addr = ksb + ((kg * 16 + lrow) * 72 + kk * 16 + lkb) * 2;
                LDMX4(b0, b1, b2, b3, addr);
                MMA16816(S[kg * 2 + 0], qa[kk], b0, b2);
                MMA16816(S[kg * 2 + 1], qa[kk], b1, b3);
            }
        }
        // scale
        #pragma unroll
        for (int j = 0; j < 8; j++) {
            S[j][0] *= 0.125f; S[j][1] *= 0.125f; S[j][2] *= 0.125f; S[j][3] *= 0.125f;
        }

        // online softmax (rows r=lane>>2 and r+8)
        float cm0 = -1e30f, cm1 = -1e30f;
        #pragma unroll
        for (int j = 0; j < 8; j++) {
            cm0 = fmaxf(cm0, fmaxf(S[j][0], S[j][1]));
            cm1 = fmaxf(cm1, fmaxf(S[j][2], S[j][3]));
        }
        cm0 = quadMax(cm0); cm1 = quadMax(cm1);
        float mn0 = fmaxf(m0, cm0), mn1 = fmaxf(m1, cm1);
        float f0 = __expf(m0 - mn0), f1 = __expf(m1 - mn1);
        float sum0 = 0.f, sum1 = 0.f;
        #pragma unroll
        for (int j = 0; j < 8; j++) {
            S[j][0] = __expf(S[j][0] - mn0); S[j][1] = __expf(S[j][1] - mn0);
            S[j][2] = __expf(S[j][2] - mn1); S[j][3] = __expf(S[j][3] - mn1);
            sum0 += S[j][0] + S[j][1];
            sum1 += S[j][2] + S[j][3];
        }
        sum0 = quadSum(sum0); sum1 = quadSum(sum1);
        l0 = l0 * f0 + sum0; l1 = l1 * f1 + sum1;
        m0 = mn0; m1 = mn1;
        #pragma unroll
        for (int j = 0; j < 8; j++) {
            O[j][0] *= f0; O[j][1] *= f0; O[j][2] *= f1; O[j][3] *= f1;
        }

        // PV: P (regs->half) @ V (ldmatrix.trans), accumulate into O
        #pragma unroll
        for (int s16 = 0; s16 < 4; s16++) {
            uint32_t pa[4];
            pa[0] = packh2(S[s16 * 2 + 0][0], S[s16 * 2 + 0][1]);
            pa[1] = packh2(S[s16 * 2 + 0][2], S[s16 * 2 + 0][3]);
            pa[2] = packh2(S[s16 * 2 + 1][0], S[s16 * 2 + 1][1]);
            pa[3] = packh2(S[s16 * 2 + 1][2], S[s16 * 2 + 1][3]);
            #pragma unroll
            for (int nb = 0; nb < 4; nb++) {
                uint32_t v0, v1, v2, v3;
                uint32_t addr = vsb + ((s16 * 16 + lrow) * 72 + nb * 16 + lkb) * 2;
                LDMX4T(v0, v1, v2, v3, addr);
                MMA16816(O[nb * 2 + 0], pa, v0, v1);
                MMA16816(O[nb * 2 + 1], pa, v2, v3);
            }
        }
        __syncthreads();
    }

    // normalize + write (half) to g_attnout_h[s*1024 + q, h*64 + d]
    float inv0 = 1.f / l0, inv1 = 1.f / l1;
    int r = lane >> 2;
    int grow0 = s * 1024 + q0 + wq0 + r;
    __half* Ob = g_attnout_h + (size_t)grow0 * 1024 + h * 64;
    #pragma unroll
    for (int j = 0; j < 8; j++) {
        int colo = j * 8 + (lane & 3) * 2;
        *(__half2*)(Ob + colo)              = __floats2half2_rn(O[j][0] * inv0, O[j][1] * inv0);
        *(__half2*)(Ob + 8 * 1024 + colo)   = __floats2half2_rn(O[j][2] * inv1, O[j][3] * inv1);
    }
}

// ---------------- orchestration ----------------
extern "C" void kernel_launch(void* const* d_in, const int* in_sizes, int n_in,
                              void* d_out, int out_size) {
    const float* x           = (const float*)d_in[0];
    const float* c           = (const float*)d_in[1];
    const float* attn_qkv_w  = (const float*)d_in[2];
    const float* attn_qkv_b  = (const float*)d_in[3];
    const float* attn_proj_w = (const float*)d_in[4];
    const float* attn_proj_b = (const float*)d_in[5];
    const float* crs_qkv_w   = (const float*)d_in[6];
    const float* crs_qkv_b   = (const float*)d_in[7];
    const float* crs_proj_w  = (const float*)d_in[8];
    const float* crs_proj_b  = (const float*)d_in[9];
    const float* mlp_fc1_w   = (const float*)d_in[10];
    const float* mlp_fc1_b   = (const float*)d_in[11];
    const float* mlp_fc2_w   = (const float*)d_in[12];
    const float* mlp_fc2_b   = (const float*)d_in[13];
    const float* ada_w       = (const float*)d_in[14];
    const float* ada_b       = (const float*)d_in[15];
    float* out = (float*)d_out;

    __half *qkv, *xln, *attnout, *hbuf, *wt;
    cudaGetSymbolAddress((void**)&qkv, g_qkv_h);
    cudaGetSymbolAddress((void**)&xln, g_xln_h);
    cudaGetSymbolAddress((void**)&attnout, g_attnout_h);
    cudaGetSymbolAddress((void**)&hbuf, g_hbuf_h);
    cudaGetSymbolAddress((void**)&wt, g_wt);

    dim3 tb(32, 8);
    transpose_cvt<<<dim3(96, 32),  tb>>>(attn_qkv_w,  wt + WT_ATTN_QKV,  1024, 3072);
    transpose_cvt<<<dim3(96, 32),  tb>>>(crs_qkv_w,   wt + WT_CRS_QKV,   1024, 3072);
    transpose_cvt<<<dim3(32, 32),  tb>>>(attn_proj_w, wt + WT_ATTN_PROJ, 1024, 1024);
    transpose_cvt<<<dim3(32, 32),  tb>>>(crs_proj_w,  wt + WT_CRS_PROJ,  1024, 1024);
    transpose_cvt<<<dim3(128, 32), tb>>>(mlp_fc1_w,   wt + WT_FC1,       1024, 4096);
    transpose_cvt<<<dim3(32, 128), tb>>>(mlp_fc2_w,   wt + WT_FC2,       4096, 1024);

    mod_kernel<<<dim3(36, 4), 256>>>(c, ada_w, ada_b);

    // ---- self-attention (MSA): shOff=0, gate off=2048 ----
    ln_mod_kernel<<<4096, 256>>>(x, xln, 0);
    hgemm<0, 1><<<dim3(24, 32), 256>>>(xln, wt + WT_ATTN_QKV, qkv, 1024, 3072,
                                       attn_qkv_b, nullptr, 0);
    flash_attn<<<dim3(8, 64), 256>>>(0);
    hgemm<2, 0><<<dim3(8, 32), 256>>>(attnout, wt + WT_ATTN_PROJ, out, 1024, 1024,
                                      attn_proj_b, x, 2048);

    // ---- cross-attention (MCA): LN reads post-MSA, residual base = original x ----
    ln_mod_kernel<<<4096, 256>>>(out, xln, 3072);
    hgemm<0, 1><<<dim3(24, 32), 256>>>(xln, wt + WT_CRS_QKV, qkv, 1024, 3072,
                                       crs_qkv_b, nullptr, 0);
    flash_attn<<<dim3(8, 64), 256>>>(1);
    hgemm<2, 0><<<dim3(8, 32), 256>>>(attnout, wt + WT_CRS_PROJ, out, 1024, 1024,
                                      crs_proj_b, x, 5120);

    // ---- MLP: shOff=6144, gate off=8192 ----
    ln_mod_kernel<<<4096, 256>>>(out, xln, 6144);
    hgemm<1, 1><<<dim3(32, 32), 256>>>(xln, wt + WT_FC1, hbuf, 1024, 4096,
                                       mlp_fc1_b, nullptr, 0);
    hgemm<2, 0><<<dim3(8, 32), 256>>>(hbuf, wt + WT_FC2, out, 4096, 1024,
                                      mlp_fc2_b, out, 8192);
}

// round 8
// speedup vs baseline: 5.6869x; 1.0112x over previous
#include <cuda_runtime.h>
#include <cuda_fp16.h>
#include <math.h>
#include <stdint.h>

// ---------------- scratch (static device globals: allocation-free) ----------------
__device__ float  g_mod[4 * 9216];                  // (b,half) x 9*1024
__device__ __half g_qkv_h[4096 * 3072];             // qkv projections (half)
__device__ __half g_xln_h[4096 * 1024];             // LN+mod output (half, GEMM A)
__device__ __half g_attnout_h[4096 * 1024];         // attention output (half, GEMM A)
__device__ __half g_hbuf_h[4096 * 4096];            // MLP hidden (half, GEMM A)
__device__ __half g_wt[16777216];                   // transposed half weights [N,K]

#define WT_ATTN_QKV  0
#define WT_CRS_QKV   3145728
#define WT_ATTN_PROJ 6291456
#define WT_CRS_PROJ  7340032
#define WT_FC1       8388608
#define WT_FC2       12582912

__device__ __forceinline__ uint32_t smem_to_u32(const void* p) {
    uint32_t a;
    asm("{ .reg .u64 t; cvta.to.shared.u64 t, %1; cvt.u32.u64 %0, t; }" : "=r"(a) : "l"(p));
    return a;
}
__device__ __forceinline__ uint32_t packh2(float a, float b) {
    __half2 h = __floats2half2_rn(a, b);
    return *(uint32_t*)&h;
}

// ---------------- reduction helpers ----------------
__device__ __forceinline__ float warpSum(float v) {
    #pragma unroll
    for (int o = 16; o > 0; o >>= 1) v += __shfl_xor_sync(0xffffffffu, v, o);
    return v;
}
__device__ __forceinline__ float warpMax(float v) {
    #pragma unroll
    for (int o = 16; o > 0; o >>= 1) v = fmaxf(v, __shfl_xor_sync(0xffffffffu, v, o));
    return v;
}
__device__ __forceinline__ float quadMax(float v) {
    v = fmaxf(v, __shfl_xor_sync(0xffffffffu, v, 1));
    v = fmaxf(v, __shfl_xor_sync(0xffffffffu, v, 2));
    return v;
}
__device__ __forceinline__ float quadSum(float v) {
    v += __shfl_xor_sync(0xffffffffu, v, 1);
    v += __shfl_xor_sync(0xffffffffu, v, 2);
    return v;
}

// ---------------- mma / ldmatrix / cp.async macros ----------------
#define LDMX4(r0, r1, r2, r3, addr) \
    asm volatile("ldmatrix.sync.aligned.m8n8.x4.shared.b16 {%0,%1,%2,%3}, [%4];" \
                 : "=r"(r0), "=r"(r1), "=r"(r2), "=r"(r3) : "r"(addr))
#define LDMX4T(r0, r1, r2, r3, addr) \
    asm volatile("ldmatrix.sync.aligned.m8n8.x4.trans.shared.b16 {%0,%1,%2,%3}, [%4];" \
                 : "=r"(r0), "=r"(r1), "=r"(r2), "=r"(r3) : "r"(addr))
#define MMA16816(d, a, b0v, b1v) \
    asm volatile("mma.sync.aligned.m16n8k16.row.col.f32.f16.f16.f32 " \
                 "{%0,%1,%2,%3}, {%4,%5,%6,%7}, {%8,%9}, {%0,%1,%2,%3};" \
                 : "+f"((d)[0]), "+f"((d)[1]), "+f"((d)[2]), "+f"((d)[3]) \
                 : "r"((a)[0]), "r"((a)[1]), "r"((a)[2]), "r"((a)[3]), "r"(b0v), "r"(b1v))
#define CP_ASYNC16(dst, src) \
    asm volatile("cp.async.cg.shared.global [%0], [%1], 16;" :: "r"(dst), "l"(src))
#define CP_COMMIT() asm volatile("cp.async.commit_group;")
#define CP_WAIT1()  asm volatile("cp.async.wait_group 1;")
#define CP_WAIT0()  asm volatile("cp.async.wait_group 0;")

// ---------------- weight transpose + fp16 convert: Wt[n][k] = (half)W[k][n] ----------------
__global__ void transpose_cvt(const float* __restrict__ W, __half* __restrict__ Wt, int K, int N) {
    __shared__ float tile[32][33];
    int n0 = blockIdx.x * 32, k0 = blockIdx.y * 32;
    int tx = threadIdx.x, ty = threadIdx.y;   // (32,8)
    #pragma unroll
    for (int i = 0; i < 4; i++)
        tile[ty * 4 + i][tx] = W[(size_t)(k0 + ty * 4 + i) * N + n0 + tx];
    __syncthreads();
    #pragma unroll
    for (int i = 0; i < 4; i++)
        Wt[(size_t)(n0 + ty * 4 + i) * K + k0 + tx] = __float2half_rn(tile[tx][ty * 4 + i]);
}

// ---------------- adaLN modulation ----------------
__global__ void mod_kernel(const float* __restrict__ c,
                           const float* __restrict__ ada_w,
                           const float* __restrict__ ada_b) {
    __shared__ float sc[1024];
    int bj = blockIdx.y;
    int o  = blockIdx.x * 256 + threadIdx.x;
    const float* crow = c + bj * 1024;
    for (int i = threadIdx.x; i < 1024; i += 256) {
        float v = crow[i];
        sc[i] = v / (1.f + __expf(-v));
    }
    __syncthreads();
    float acc = 0.f;
    #pragma unroll 4
    for (int k = 0; k < 1024; k++)
        acc = fmaf(sc[k], ada_w[(size_t)k * 9216 + o], acc);
    g_mod[bj * 9216 + o] = acc + ada_b[o];
}

// ---------------- fused LayerNorm + modulation -> half ----------------
__global__ void ln_mod_kernel(const float* __restrict__ x, __half* __restrict__ y, int shOff) {
    int r = blockIdx.x;
    int s = r >> 10;
    int t = threadIdx.x;
    const float4* xr = (const float4*)(x + (size_t)r * 1024);
    float4 v = xr[t];
    __shared__ float sm[8];
    float ws = warpSum(v.x + v.y + v.z + v.w);
    if ((t & 31) == 0) sm[t >> 5] = ws;
    __syncthreads();
    float mu;
    { float s8 = 0.f;
      #pragma unroll
      for (int i = 0; i < 8; i++) s8 += sm[i];
      mu = s8 * (1.f / 1024.f); }
    __syncthreads();
    float dx = v.x - mu, dy = v.y - mu, dz = v.z - mu, dw = v.w - mu;
    float wv = warpSum(dx * dx + dy * dy + dz * dz + dw * dw);
    if ((t & 31) == 0) sm[t >> 5] = wv;
    __syncthreads();
    float var;
    { float s8 = 0.f;
      #pragma unroll
      for (int i = 0; i < 8; i++) s8 += sm[i];
      var = s8 * (1.f / 1024.f); }
    float inv = rsqrtf(var + 1e-6f);
    const float* m = g_mod + s * 9216 + shOff;
    float4 shv = *(const float4*)(m + t * 4);
    float4 scv = *(const float4*)(m + 1024 + t * 4);
    float ox = dx * inv * (1.f + scv.x) + shv.x;
    float oy = dy * inv * (1.f + scv.y) + shv.y;
    float oz = dz * inv * (1.f + scv.z) + shv.z;
    float ow = dw * inv * (1.f + scv.w) + shv.w;
    __half2* yr = (__half2*)(y + (size_t)r * 1024);
    yr[t * 2 + 0] = __floats2half2_rn(ox, oy);
    yr[t * 2 + 1] = __floats2half2_rn(oz, ow);
}

// ---------------- warp-MMA fp16 GEMM, cp.async double-buffered ----------------
// Dynamic smem: 2 stages x (A 128x72 + B 128x72) halves = 73728 bytes.
// MODE 0: C = acc + bias ; MODE 1: gelu(acc+bias) ; MODE 2: base + gate*(acc+bias)
template <int MODE, int OUTHALF>
__global__ void __launch_bounds__(256)
hgemm(const __half* __restrict__ A, const __half* __restrict__ Bt,
      void* __restrict__ Cv, int K, int N,
      const float* __restrict__ bias,
      const float* __restrict__ base, int gOff) {
    extern __shared__ __align__(16) uint8_t hsm[];
    uint32_t sb = smem_to_u32(hsm);
    int tid = threadIdx.x;
    int wid = tid >> 5, lane = tid & 31;
    int brow = blockIdx.y * 128, bcol = blockIdx.x * 128;
    int wr = wid & 1, wc = wid >> 1;
    int lrow = lane & 15, lkb = (lane >> 4) * 8;

    float acc[4][4][4];
    #pragma unroll
    for (int i = 0; i < 4; i++)
        #pragma unroll
        for (int j = 0; j < 4; j++)
            #pragma unroll
            for (int q = 0; q < 4; q++) acc[i][j][q] = 0.f;

    int ldr = tid >> 3, ldg = (tid & 7) * 8;   // row-within-32-group, 8-half col group
    const __half* Abase = A  + (size_t)(brow + ldr) * K + ldg;
    const __half* Bbase = Bt + (size_t)(bcol + ldr) * K + ldg;

    // stage s: A at sb + s*36864, B at sb + s*36864 + 18432. Row pitch 144 B.
    auto issue = [&](int c, int s) {
        uint32_t ab = sb + (uint32_t)s * 36864 + ldr * 144 + ldg * 2;
        uint32_t bb = ab + 18432;
        int k0 = c << 6;
        #pragma unroll
        for (int i = 0; i < 4; i++) {
            CP_ASYNC16(ab + i * 32 * 144, Abase + (size_t)(i * 32) * K + k0);
            CP_ASYNC16(bb + i * 32 * 144, Bbase + (size_t)(i * 32) * K + k0);
        }
    };

    const int T = K >> 6;
    issue(0, 0);
    CP_COMMIT();
    for (int c = 0; c < T; c++) {
        int b = c & 1;
        if (c + 1 < T) { issue(c + 1, b ^ 1); CP_COMMIT(); CP_WAIT1(); }
        else CP_WAIT0();
        __syncthreads();
        uint32_t asb = sb + (uint32_t)b * 36864;
        uint32_t bsb = asb + 18432;
        #pragma unroll
        for (int kk = 0; kk < 4; kk++) {
            uint32_t a[4][4], bfr[2][4];
            #pragma unroll
            for (int mt = 0; mt < 4; mt++) {
                uint32_t addr = asb + (wr * 64 + mt * 16 + lrow) * 144 + (kk * 16 + lkb) * 2;
                LDMX4(a[mt][0], a[mt][1], a[mt][2], a[mt][3], addr);
            }
            #pragma unroll
            for (int ng = 0; ng < 2; ng++) {
                uint32_t addr = bsb + (wc * 32 + ng * 16 + lrow) * 144 + (kk * 16 + lkb) * 2;
                LDMX4(bfr[ng][0], bfr[ng][1], bfr[ng][2], bfr[ng][3], addr);
            }
            #pragma unroll
            for (int mt = 0; mt < 4; mt++)
                #pragma unroll
                for (int j = 0; j < 4; j++)
                    MMA16816(acc[mt][j], a[mt], bfr[j >> 1][j & 1], bfr[j >> 1][(j & 1) + 2]);
        }
        __syncthreads();
    }

    int cbase = bcol + wc * 32;
    #pragma unroll
    for (int mt = 0; mt < 4; mt++) {
        int r0 = brow + wr * 64 + mt * 16 + (lane >> 2);
        #pragma unroll
        for (int half_ = 0; half_ < 2; half_++) {
            int row = r0 + half_ * 8;
            const float* gp = (MODE == 2) ? (g_mod + (row >> 10) * 9216 + gOff) : nullptr;
            #pragma unroll
            for (int j = 0; j < 4; j++) {
                int col = cbase + j * 8 + (lane & 3) * 2;
                float v0 = acc[mt][j][half_ * 2 + 0] + bias[col];
                float v1 = acc[mt][j][half_ * 2 + 1] + bias[col + 1];
                if (MODE == 1) {
                    float u0 = 0.7978845608028654f * (v0 + 0.044715f * v0 * v0 * v0);
                    float u1 = 0.7978845608028654f * (v1 + 0.044715f * v1 * v1 * v1);
                    v0 = __fdividef(v0, 1.f + __expf(-2.f * u0));
                    v1 = __fdividef(v1, 1.f + __expf(-2.f * u1));
                } else if (MODE == 2) {
                    const float* basep = base + (size_t)row * N + col;
                    v0 = basep[0] + gp[col] * v0;
                    v1 = basep[1] + gp[col + 1] * v1;
                }
                if (OUTHALF) {
                    *(__half2*)((__half*)Cv + (size_t)row * N + col) = __floats2half2_rn(v0, v1);
                } else {
                    *(float2*)((float*)Cv + (size_t)row * N + col) = make_float2(v0, v1);
                }
            }
        }
    }
}

// ---------------- fused flash attention (HMMA, online softmax, cp.async 2-stage KV) ----
// grid = (8 q-blocks, 64 zh). CTA: 8 warps x 16 query rows. Keys in 16 chunks of 64.
// Static smem 36864 B = 2 stages x (K 64x72 + V 64x72). Q borrows stage 0 at init.
__global__ void __launch_bounds__(256)
flash_attn(int cross) {
    __shared__ __align__(16) uint8_t fsm[36864];
    uint32_t sb = smem_to_u32(fsm);

    int zh = blockIdx.y, s = zh >> 4, h = zh & 15;
    int ks = cross ? (s ^ 1) : s;
    int q0 = blockIdx.x * 128;
    int tid = threadIdx.x, wid = tid >> 5, lane = tid & 31;
    int lrow = lane & 15, lkb = (lane >> 4) * 8;
    int wq0 = wid * 16;

    // ---- load Q tile (128 x 64 half) into stage-0 space, extract frags ----
    #pragma unroll
    for (int i = 0; i < 4; i++) {
        int idx = i * 256 + tid;
        int r = idx >> 3, g = (idx & 7) * 8;
        *(uint4*)(fsm + r * 144 + g * 2) =
            *(const uint4*)(g_qkv_h + (size_t)(s * 1024 + q0 + r) * 3072 + h * 64 + g);
    }
    __syncthreads();
    uint32_t qa[4][4];
    {
        __half2 hs = __floats2half2_rn(0.125f, 0.125f);
        #pragma unroll
        for (int kk = 0; kk < 4; kk++) {
            uint32_t addr = sb + (wq0 + lrow) * 144 + (kk * 16 + lkb) * 2;
            LDMX4(qa[kk][0], qa[kk][1], qa[kk][2], qa[kk][3], addr);
            #pragma unroll
            for (int i = 0; i < 4; i++) {
                __half2 t = __hmul2(*(__half2*)&qa[kk][i], hs);   // fold 1/8 (exact)
                qa[kk][i] = *(uint32_t*)&t;
            }
        }
    }
    __syncthreads();

    // ---- KV pipeline ----
    int kvr = tid >> 3, kvg = (tid & 7) * 8;           // rows 0..31 per i-step
    const __half* KVbase = g_qkv_h + (size_t)(ks * 1024 + kvr) * 3072 + h * 64 + kvg;
    auto issue_kv = [&](int c, int st) {
        uint32_t kb = sb + (uint32_t)st * 18432 + kvr * 144 + kvg * 2;
        int k0 = c << 6;
        #pragma unroll
        for (int i = 0; i < 2; i++) {
            const __half* src = KVbase + (size_t)(k0 + i * 32) * 3072;
            CP_ASYNC16(kb + i * 32 * 144,        src + 1024);   // K
            CP_ASYNC16(kb + i * 32 * 144 + 9216, src + 2048);   // V
        }
    };

    float O[8][4];
    #pragma unroll
    for (int j = 0; j < 8; j++)
        #pragma unroll
        for (int q = 0; q < 4; q++) O[j][q] = 0.f;
    float m0 = -1e30f, m1 = -1e30f, l0 = 0.f, l1 = 0.f;

    issue_kv(0, 0);
    CP_COMMIT();
    for (int c = 0; c < 16; c++) {
        int st = c & 1;
        if (c < 15) { issue_kv(c + 1, st ^ 1); CP_COMMIT(); CP_WAIT1(); }
        else CP_WAIT0();
        __syncthreads();
        uint32_t ksb = sb + (uint32_t)st * 18432;
        uint32_t vsb = ksb + 9216;

        // S = (Q/8) @ K^T (m16 x n64), fp32
        float S[8][4];
        #pragma unroll
        for (int j = 0; j < 8; j++)
            #pragma unroll
            for (int q = 0; q < 4; q++) S[j][q] = 0.f;
        #pragma unroll
        for (int kk = 0; kk < 4; kk++) {
            #pragma unroll
            for (int kg = 0; kg < 4; kg++) {
                uint32_t b0, b1, b2, b3;
                uint32_t addr = ksb + (kg * 16 + lrow) * 144 + (kk * 16 + lkb) * 2;
                LDMX4(b0, b1, b2, b3, addr);
                MMA16816(S[kg * 2 + 0], qa[kk], b0, b2);
                MMA16816(S[kg * 2 + 1], qa[kk], b1, b3);
            }
        }

        // online softmax (rows r=lane>>2 and r+8)
        float cm0 = -1e30f, cm1 = -1e30f;
        #pragma unroll
        for (int j = 0; j < 8; j++) {
            cm0 = fmaxf(cm0, fmaxf(S[j][0], S[j][1]));
            cm1 = fmaxf(cm1, fmaxf(S[j][2], S[j][3]));
        }
        cm0 = quadMax(cm0); cm1 = quadMax(cm1);
        float mn0 = fmaxf(m0, cm0), mn1 = fmaxf(m1, cm1);
        float f0 = __expf(m0 - mn0), f1 = __expf(m1 - mn1);
        float sum0 = 0.f, sum1 = 0.f;
        #pragma unroll
        for (int j = 0; j < 8; j++) {
            S[j][0] = __expf(S[j][0] - mn0); S[j][1] = __expf(S[j][1] - mn0);
            S[j][2] = __expf(S[j][2] - mn1); S[j][3] = __expf(S[j][3] - mn1);
            sum0 += S[j][0] + S[j][1];
            sum1 += S[j][2] + S[j][3];
        }
        sum0 = quadSum(sum0); sum1 = quadSum(sum1);
        l0 = l0 * f0 + sum0; l1 = l1 * f1 + sum1;
        m0 = mn0; m1 = mn1;
        #pragma unroll
        for (int j = 0; j < 8; j++) {
            O[j][0] *= f0; O[j][1] *= f0; O[j][2] *= f1; O[j][3] *= f1;
        }

        // PV: P (regs->half) @ V (ldmatrix.trans), accumulate into O
        #pragma unroll
        for (int s16 = 0; s16 < 4; s16++) {
            uint32_t pa[4];
            pa[0] = packh2(S[s16 * 2 + 0][0], S[s16 * 2 + 0][1]);
            pa[1] = packh2(S[s16 * 2 + 0][2], S[s16 * 2 + 0][3]);
            pa[2] = packh2(S[s16 * 2 + 1][0], S[s16 * 2 + 1][1]);
            pa[3] = packh2(S[s16 * 2 + 1][2], S[s16 * 2 + 1][3]);
            #pragma unroll
            for (int nb = 0; nb < 4; nb++) {
                uint32_t v0, v1, v2, v3;
                uint32_t addr = vsb + (s16 * 16 + lrow) * 144 + (nb * 16 + lkb) * 2;
                LDMX4T(v0, v1, v2, v3, addr);
                MMA16816(O[nb * 2 + 0], pa, v0, v1);
                MMA16816(O[nb * 2 + 1], pa, v2, v3);
            }
        }
        __syncthreads();
    }

    // normalize + write (half)
    float inv0 = 1.f / l0, inv1 = 1.f / l1;
    int r = lane >> 2;
    int grow0 = s * 1024 + q0 + wq0 + r;
    __half* Ob = g_attnout_h + (size_t)grow0 * 1024 + h * 64;
    #pragma unroll
    for (int j = 0; j < 8; j++) {
        int colo = j * 8 + (lane & 3) * 2;
        *(__half2*)(Ob + colo)            = __floats2half2_rn(O[j][0] * inv0, O[j][1] * inv0);
        *(__half2*)(Ob + 8 * 1024 + colo) = __floats2half2_rn(O[j][2] * inv1, O[j][3] * inv1);
    }
}

// ---------------- orchestration ----------------
extern "C" void kernel_launch(void* const* d_in, const int* in_sizes, int n_in,
                              void* d_out, int out_size) {
    const float* x           = (const float*)d_in[0];
    const float* c           = (const float*)d_in[1];
    const float* attn_qkv_w  = (const float*)d_in[2];
    const float* attn_qkv_b  = (const float*)d_in[3];
    const float* attn_proj_w = (const float*)d_in[4];
    const float* attn_proj_b = (const float*)d_in[5];
    const float* crs_qkv_w   = (const float*)d_in[6];
    const float* crs_qkv_b   = (const float*)d_in[7];
    const float* crs_proj_w  = (const float*)d_in[8];
    const float* crs_proj_b  = (const float*)d_in[9];
    const float* mlp_fc1_w   = (const float*)d_in[10];
    const float* mlp_fc1_b   = (const float*)d_in[11];
    const float* mlp_fc2_w   = (const float*)d_in[12];
    const float* mlp_fc2_b   = (const float*)d_in[13];
    const float* ada_w       = (const float*)d_in[14];
    const float* ada_b       = (const float*)d_in[15];
    float* out = (float*)d_out;

    __half *qkv, *xln, *attnout, *hbuf, *wt;
    cudaGetSymbolAddress((void**)&qkv, g_qkv_h);
    cudaGetSymbolAddress((void**)&xln, g_xln_h);
    cudaGetSymbolAddress((void**)&attnout, g_attnout_h);
    cudaGetSymbolAddress((void**)&hbuf, g_hbuf_h);
    cudaGetSymbolAddress((void**)&wt, g_wt);

    const int HS = 73728;
    cudaFuncSetAttribute(hgemm<0, 1>, cudaFuncAttributeMaxDynamicSharedMemorySize, HS);
    cudaFuncSetAttribute(hgemm<1, 1>, cudaFuncAttributeMaxDynamicSharedMemorySize, HS);
    cudaFuncSetAttribute(hgemm<2, 0>, cudaFuncAttributeMaxDynamicSharedMemorySize, HS);

    dim3 tb(32, 8);
    transpose_cvt<<<dim3(96, 32),  tb>>>(attn_qkv_w,  wt + WT_ATTN_QKV,  1024, 3072);
    transpose_cvt<<<dim3(96, 32),  tb>>>(crs_qkv_w,   wt + WT_CRS_QKV,   1024, 3072);
    transpose_cvt<<<dim3(32, 32),  tb>>>(attn_proj_w, wt + WT_ATTN_PROJ, 1024, 1024);
    transpose_cvt<<<dim3(32, 32),  tb>>>(crs_proj_w,  wt + WT_CRS_PROJ,  1024, 1024);
    transpose_cvt<<<dim3(128, 32), tb>>>(mlp_fc1_w,   wt + WT_FC1,       1024, 4096);
    transpose_cvt<<<dim3(32, 128), tb>>>(mlp_fc2_w,   wt + WT_FC2,       4096, 1024);

    mod_kernel<<<dim3(36, 4), 256>>>(c, ada_w, ada_b);

    // ---- self-attention (MSA): shOff=0, gate off=2048 ----
    ln_mod_kernel<<<4096, 256>>>(x, xln, 0);
    hgemm<0, 1><<<dim3(24, 32), 256, HS>>>(xln, wt + WT_ATTN_QKV, qkv, 1024, 3072,
                                           attn_qkv_b, nullptr, 0);
    flash_attn<<<dim3(8, 64), 256>>>(0);
    hgemm<2, 0><<<dim3(8, 32), 256, HS>>>(attnout, wt + WT_ATTN_PROJ, out, 1024, 1024,
                                          attn_proj_b, x, 2048);

    // ---- cross-attention (MCA): LN reads post-MSA, residual base = original x ----
    ln_mod_kernel<<<4096, 256>>>(out, xln, 3072);
    hgemm<0, 1><<<dim3(24, 32), 256, HS>>>(xln, wt + WT_CRS_QKV, qkv, 1024, 3072,
                                           crs_qkv_b, nullptr, 0);
    flash_attn<<<dim3(8, 64), 256>>>(1);
    hgemm<2, 0><<<dim3(8, 32), 256, HS>>>(attnout, wt + WT_CRS_PROJ, out, 1024, 1024,
                                          crs_proj_b, x, 5120);

    // ---- MLP: shOff=6144, gate off=8192 ----
    ln_mod_kernel<<<4096, 256>>>(out, xln, 6144);
    hgemm<1, 1><<<dim3(32, 32), 256, HS>>>(xln, wt + WT_FC1, hbuf, 1024, 4096,
                                           mlp_fc1_b, nullptr, 0);
    hgemm<2, 0><<<dim3(8, 32), 256, HS>>>(hbuf, wt + WT_FC2, out, 4096, 1024,
                                          mlp_fc2_b, out, 8192);
}

// round 9
// speedup vs baseline: 5.9058x; 1.0385x over previous
#include <cuda_runtime.h>
#include <cuda_fp16.h>
#include <math.h>
#include <stdint.h>

// ---------------- scratch (static device globals: allocation-free) ----------------
__device__ float  g_mod[4 * 9216];                  // (b,half) x 9*1024
__device__ __half g_qkv_h[4096 * 3072];             // qkv projections (half)
__device__ __half g_xln_h[4096 * 1024];             // LN+mod output (half, GEMM A)
__device__ __half g_attnout_h[4096 * 1024];         // attention output (half, GEMM A)
__device__ __half g_hbuf_h[4096 * 4096];            // MLP hidden (half, GEMM A)
__device__ __half g_wt[16777216];                   // transposed half weights [N,K]

#define WT_ATTN_QKV  0
#define WT_CRS_QKV   3145728
#define WT_ATTN_PROJ 6291456
#define WT_CRS_PROJ  7340032
#define WT_FC1       8388608
#define WT_FC2       12582912

__device__ __forceinline__ uint32_t smem_to_u32(const void* p) {
    uint32_t a;
    asm("{ .reg .u64 t; cvta.to.shared.u64 t, %1; cvt.u32.u64 %0, t; }" : "=r"(a) : "l"(p));
    return a;
}
__device__ __forceinline__ uint32_t packh2(float a, float b) {
    __half2 h = __floats2half2_rn(a, b);
    return *(uint32_t*)&h;
}

// ---------------- reduction helpers ----------------
__device__ __forceinline__ float warpSum(float v) {
    #pragma unroll
    for (int o = 16; o > 0; o >>= 1) v += __shfl_xor_sync(0xffffffffu, v, o);
    return v;
}
__device__ __forceinline__ float quadMax(float v) {
    v = fmaxf(v, __shfl_xor_sync(0xffffffffu, v, 1));
    v = fmaxf(v, __shfl_xor_sync(0xffffffffu, v, 2));
    return v;
}
__device__ __forceinline__ float quadSum(float v) {
    v += __shfl_xor_sync(0xffffffffu, v, 1);
    v += __shfl_xor_sync(0xffffffffu, v, 2);
    return v;
}

// ---------------- mma / ldmatrix / cp.async macros ----------------
#define LDMX4(r0, r1, r2, r3, addr) \
    asm volatile("ldmatrix.sync.aligned.m8n8.x4.shared.b16 {%0,%1,%2,%3}, [%4];" \
                 : "=r"(r0), "=r"(r1), "=r"(r2), "=r"(r3) : "r"(addr))
#define LDMX4T(r0, r1, r2, r3, addr) \
    asm volatile("ldmatrix.sync.aligned.m8n8.x4.trans.shared.b16 {%0,%1,%2,%3}, [%4];" \
                 : "=r"(r0), "=r"(r1), "=r"(r2), "=r"(r3) : "r"(addr))
#define MMA16816(d, a, b0v, b1v) \
    asm volatile("mma.sync.aligned.m16n8k16.row.col.f32.f16.f16.f32 " \
                 "{%0,%1,%2,%3}, {%4,%5,%6,%7}, {%8,%9}, {%0,%1,%2,%3};" \
                 : "+f"((d)[0]), "+f"((d)[1]), "+f"((d)[2]), "+f"((d)[3]) \
                 : "r"((a)[0]), "r"((a)[1]), "r"((a)[2]), "r"((a)[3]), "r"(b0v), "r"(b1v))
#define CP_ASYNC16(dst, src) \
    asm volatile("cp.async.cg.shared.global [%0], [%1], 16;" :: "r"(dst), "l"(src))
#define CP_COMMIT() asm volatile("cp.async.commit_group;")
#define CP_WAIT1()  asm volatile("cp.async.wait_group 1;")
#define CP_WAIT0()  asm volatile("cp.async.wait_group 0;")

// ---------------- multi-weight transpose + fp16 convert: Wt[n][k] = (half)W[k][n] --------
__global__ void transpose_multi(
    const float* W0, __half* T0, int K0, int N0, int e0,
    const float* W1, __half* T1, int K1, int N1, int e1,
    const float* W2, __half* T2, int K2, int N2, int e2,
    const float* W3, __half* T3, int K3, int N3, int e3) {
    __shared__ float tile[32][33];
    int id = blockIdx.x;
    const float* W; __half* Wt; int K, N, local;
    if (id < e0)      { W = W0; Wt = T0; K = K0; N = N0; local = id; }
    else if (id < e1) { W = W1; Wt = T1; K = K1; N = N1; local = id - e0; }
    else if (id < e2) { W = W2; Wt = T2; K = K2; N = N2; local = id - e1; }
    else              { W = W3; Wt = T3; K = K3; N = N3; local = id - e2; }
    int nbx = N >> 5;
    int n0 = (local % nbx) * 32, k0 = (local / nbx) * 32;
    int tx = threadIdx.x, ty = threadIdx.y;   // (32,8)
    #pragma unroll
    for (int i = 0; i < 4; i++)
        tile[ty * 4 + i][tx] = W[(size_t)(k0 + ty * 4 + i) * N + n0 + tx];
    __syncthreads();
    #pragma unroll
    for (int i = 0; i < 4; i++)
        Wt[(size_t)(n0 + ty * 4 + i) * K + k0 + tx] = __float2half_rn(tile[tx][ty * 4 + i]);
}

// ---------------- adaLN modulation ----------------
__global__ void mod_kernel(const float* __restrict__ c,
                           const float* __restrict__ ada_w,
                           const float* __restrict__ ada_b) {
    __shared__ float sc[1024];
    int bj = blockIdx.y;
    int o  = blockIdx.x * 256 + threadIdx.x;
    const float* crow = c + bj * 1024;
    for (int i = threadIdx.x; i < 1024; i += 256) {
        float v = crow[i];
        sc[i] = v / (1.f + __expf(-v));
    }
    __syncthreads();
    float acc = 0.f;
    #pragma unroll 4
    for (int k = 0; k < 1024; k++)
        acc = fmaf(sc[k], ada_w[(size_t)k * 9216 + o], acc);
    g_mod[bj * 9216 + o] = acc + ada_b[o];
}

// ---------------- fused LayerNorm + modulation -> half ----------------
__global__ void ln_mod_kernel(const float* __restrict__ x, __half* __restrict__ y, int shOff) {
    int r = blockIdx.x;
    int s = r >> 10;
    int t = threadIdx.x;
    const float4* xr = (const float4*)(x + (size_t)r * 1024);
    float4 v = xr[t];
    __shared__ float sm[8];
    float ws = warpSum(v.x + v.y + v.z + v.w);
    if ((t & 31) == 0) sm[t >> 5] = ws;
    __syncthreads();
    float mu;
    { float s8 = 0.f;
      #pragma unroll
      for (int i = 0; i < 8; i++) s8 += sm[i];
      mu = s8 * (1.f / 1024.f); }
    __syncthreads();
    float dx = v.x - mu, dy = v.y - mu, dz = v.z - mu, dw = v.w - mu;
    float wv = warpSum(dx * dx + dy * dy + dz * dz + dw * dw);
    if ((t & 31) == 0) sm[t >> 5] = wv;
    __syncthreads();
    float var;
    { float s8 = 0.f;
      #pragma unroll
      for (int i = 0; i < 8; i++) s8 += sm[i];
      var = s8 * (1.f / 1024.f); }
    float inv = rsqrtf(var + 1e-6f);
    const float* m = g_mod + s * 9216 + shOff;
    float4 shv = *(const float4*)(m + t * 4);
    float4 scv = *(const float4*)(m + 1024 + t * 4);
    float ox = dx * inv * (1.f + scv.x) + shv.x;
    float oy = dy * inv * (1.f + scv.y) + shv.y;
    float oz = dz * inv * (1.f + scv.z) + shv.z;
    float ow = dw * inv * (1.f + scv.w) + shv.w;
    __half2* yr = (__half2*)(y + (size_t)r * 1024);
    yr[t * 2 + 0] = __floats2half2_rn(ox, oy);
    yr[t * 2 + 1] = __floats2half2_rn(oz, ow);
}

// ---------------- warp-MMA fp16 GEMM, 3-stage cp.async pipeline, 2 CTAs/SM ----------------
// Dynamic smem: 3 stages x (A 128x72 + B 128x72) halves = 110592 bytes.
// MODE 0: C = acc + bias ; MODE 1: gelu(acc+bias) ; MODE 2: base + gate*(acc+bias)
template <int MODE, int OUTHALF>
__global__ void __launch_bounds__(256, 2)
hgemm(const __half* __restrict__ A, const __half* __restrict__ Bt,
      void* __restrict__ Cv, int K, int N,
      const float* __restrict__ bias,
      const float* __restrict__ base, int gOff) {
    extern __shared__ __align__(16) uint8_t hsm[];
    uint32_t sb = smem_to_u32(hsm);
    int tid = threadIdx.x;
    int wid = tid >> 5, lane = tid & 31;
    int brow = blockIdx.y * 128, bcol = blockIdx.x * 128;
    int wr = wid & 1, wc = wid >> 1;
    int lrow = lane & 15, lkb = (lane >> 4) * 8;

    float acc[4][4][4];
    #pragma unroll
    for (int i = 0; i < 4; i++)
        #pragma unroll
        for (int j = 0; j < 4; j++)
            #pragma unroll
            for (int q = 0; q < 4; q++) acc[i][j][q] = 0.f;

    int ldr = tid >> 3, ldg = (tid & 7) * 8;
    const __half* Abase = A  + (size_t)(brow + ldr) * K + ldg;
    const __half* Bbase = Bt + (size_t)(bcol + ldr) * K + ldg;

    // stage s: A at sb + s*36864, B at +18432. Row pitch 144 B.
    auto issue = [&](int c, int s) {
        uint32_t ab = sb + (uint32_t)s * 36864 + ldr * 144 + ldg * 2;
        uint32_t bb = ab + 18432;
        int k0 = c << 6;
        #pragma unroll
        for (int i = 0; i < 4; i++) {
            CP_ASYNC16(ab + i * 32 * 144, Abase + (size_t)(i * 32) * K + k0);
            CP_ASYNC16(bb + i * 32 * 144, Bbase + (size_t)(i * 32) * K + k0);
        }
    };

    const int T = K >> 6;
    issue(0, 0); CP_COMMIT();
    issue(1, 1); CP_COMMIT();
    int st = 0, stn = 2;
    for (int c = 0; c < T; c++) {
        if (c + 2 < T) CP_WAIT1(); else CP_WAIT0();
        __syncthreads();
        if (c + 2 < T) { issue(c + 2, stn); CP_COMMIT(); }
        uint32_t asb = sb + (uint32_t)st * 36864;
        uint32_t bsb = asb + 18432;
        #pragma unroll
        for (int kk = 0; kk < 4; kk++) {
            uint32_t a[4][4], bfr[2][4];
            #pragma unroll
            for (int mt = 0; mt < 4; mt++) {
                uint32_t addr = asb + (wr * 64 + mt * 16 + lrow) * 144 + (kk * 16 + lkb) * 2;
                LDMX4(a[mt][0], a[mt][1], a[mt][2], a[mt][3], addr);
            }
            #pragma unroll
            for (int ng = 0; ng < 2; ng++) {
                uint32_t addr = bsb + (wc * 32 + ng * 16 + lrow) * 144 + (kk * 16 + lkb) * 2;
                LDMX4(bfr[ng][0], bfr[ng][1], bfr[ng][2], bfr[ng][3], addr);
            }
            #pragma unroll
            for (int mt = 0; mt < 4; mt++)
                #pragma unroll
                for (int j = 0; j < 4; j++)
                    MMA16816(acc[mt][j], a[mt], bfr[j >> 1][j & 1], bfr[j >> 1][(j & 1) + 2]);
        }
        st = st == 2 ? 0 : st + 1;
        stn = stn == 2 ? 0 : stn + 1;
    }

    int cbase = bcol + wc * 32;
    #pragma unroll
    for (int mt = 0; mt < 4; mt++) {
        int r0 = brow + wr * 64 + mt * 16 + (lane >> 2);
        #pragma unroll
        for (int half_ = 0; half_ < 2; half_++) {
            int row = r0 + half_ * 8;
            const float* gp = (MODE == 2) ? (g_mod + (row >> 10) * 9216 + gOff) : nullptr;
            #pragma unroll
            for (int j = 0; j < 4; j++) {
                int col = cbase + j * 8 + (lane & 3) * 2;
                float v0 = acc[mt][j][half_ * 2 + 0] + bias[col];
                float v1 = acc[mt][j][half_ * 2 + 1] + bias[col + 1];
                if (MODE == 1) {
                    float u0 = 0.7978845608028654f * (v0 + 0.044715f * v0 * v0 * v0);
                    float u1 = 0.7978845608028654f * (v1 + 0.044715f * v1 * v1 * v1);
                    v0 = __fdividef(v0, 1.f + __expf(-2.f * u0));
                    v1 = __fdividef(v1, 1.f + __expf(-2.f * u1));
                } else if (MODE == 2) {
                    const float* basep = base + (size_t)row * N + col;
                    v0 = basep[0] + gp[col] * v0;
                    v1 = basep[1] + gp[col + 1] * v1;
                }
                if (OUTHALF) {
                    *(__half2*)((__half*)Cv + (size_t)row * N + col) = __floats2half2_rn(v0, v1);
                } else {
                    *(float2*)((float*)Cv + (size_t)row * N + col) = make_float2(v0, v1);
                }
            }
        }
    }
}

// ---------------- fused flash attention (HMMA, online softmax, 3-stage cp.async KV) ------
// grid = (8 q-blocks, 64 zh). CTA: 8 warps x 16 query rows. 16 chunks of 64 keys.
// Dynamic smem 55296 = 3 stages x (K 64x72 + V 64x72). Q borrows stage 0 at init.
__global__ void __launch_bounds__(256, 2)
flash_attn(int cross) {
    extern __shared__ __align__(16) uint8_t fsm[];
    uint32_t sb = smem_to_u32(fsm);

    int zh = blockIdx.y, s = zh >> 4, h = zh & 15;
    int ks = cross ? (s ^ 1) : s;
    int q0 = blockIdx.x * 128;
    int tid = threadIdx.x, wid = tid >> 5, lane = tid & 31;
    int lrow = lane & 15, lkb = (lane >> 4) * 8;
    int wq0 = wid * 16;

    // ---- load Q tile (128 x 64 half) into stage-0 space, extract frags, fold 1/8 ----
    #pragma unroll
    for (int i = 0; i < 4; i++) {
        int idx = i * 256 + tid;
        int r = idx >> 3, g = (idx & 7) * 8;
        *(uint4*)(fsm + r * 144 + g * 2) =
            *(const uint4*)(g_qkv_h + (size_t)(s * 1024 + q0 + r) * 3072 + h * 64 + g);
    }
    __syncthreads();
    uint32_t qa[4][4];
    {
        __half2 hs = __floats2half2_rn(0.125f, 0.125f);
        #pragma unroll
        for (int kk = 0; kk < 4; kk++) {
            uint32_t addr = sb + (wq0 + lrow) * 144 + (kk * 16 + lkb) * 2;
            LDMX4(qa[kk][0], qa[kk][1], qa[kk][2], qa[kk][3], addr);
            #pragma unroll
            for (int i = 0; i < 4; i++) {
                __half2 t = __hmul2(*(__half2*)&qa[kk][i], hs);
                qa[kk][i] = *(uint32_t*)&t;
            }
        }
    }
    __syncthreads();

    // ---- KV pipeline ----
    int kvr = tid >> 3, kvg = (tid & 7) * 8;
    const __half* KVbase = g_qkv_h + (size_t)(ks * 1024 + kvr) * 3072 + h * 64 + kvg;
    auto issue_kv = [&](int c, int stg) {
        uint32_t kb = sb + (uint32_t)stg * 18432 + kvr * 144 + kvg * 2;
        int k0 = c << 6;
        #pragma unroll
        for (int i = 0; i < 2; i++) {
            const __half* src = KVbase + (size_t)(k0 + i * 32) * 3072;
            CP_ASYNC16(kb + i * 32 * 144,        src + 1024);   // K
            CP_ASYNC16(kb + i * 32 * 144 + 9216, src + 2048);   // V
        }
    };

    float O[8][4];
    #pragma unroll
    for (int j = 0; j < 8; j++)
        #pragma unroll
        for (int q = 0; q < 4; q++) O[j][q] = 0.f;
    float m0 = -1e30f, m1 = -1e30f, l0 = 0.f, l1 = 0.f;

    issue_kv(0, 0); CP_COMMIT();
    issue_kv(1, 1); CP_COMMIT();
    int st = 0, stn = 2;
    for (int c = 0; c < 16; c++) {
        if (c + 2 < 16) CP_WAIT1(); else CP_WAIT0();
        __syncthreads();
        if (c + 2 < 16) { issue_kv(c + 2, stn); CP_COMMIT(); }
        uint32_t ksb = sb + (uint32_t)st * 18432;
        uint32_t vsb = ksb + 9216;

        // S = (Q/8) @ K^T (m16 x n64), fp32
        float S[8][4];
        #pragma unroll
        for (int j = 0; j < 8; j++)
            #pragma unroll
            for (int q = 0; q < 4; q++) S[j][q] = 0.f;
        #pragma unroll
        for (int kk = 0; kk < 4; kk++) {
            #pragma unroll
            for (int kg = 0; kg < 4; kg++) {
                uint32_t b0, b1, b2, b3;
                uint32_t addr = ksb + (kg * 16 + lrow) * 144 + (kk * 16 + lkb) * 2;
                LDMX4(b0, b1, b2, b3, addr);
                MMA16816(S[kg * 2 + 0], qa[kk], b0, b2);
                MMA16816(S[kg * 2 + 1], qa[kk], b1, b3);
            }
        }

        // online softmax (rows r=lane>>2 and r+8)
        float cm0 = -1e30f, cm1 = -1e30f;
        #pragma unroll
        for (int j = 0; j < 8; j++) {
            cm0 = fmaxf(cm0, fmaxf(S[j][0], S[j][1]));
            cm1 = fmaxf(cm1, fmaxf(S[j][2], S[j][3]));
        }
        cm0 = quadMax(cm0); cm1 = quadMax(cm1);
        float mn0 = fmaxf(m0, cm0), mn1 = fmaxf(m1, cm1);
        float f0 = __expf(m0 - mn0), f1 = __expf(m1 - mn1);
        float sum0 = 0.f, sum1 = 0.f;
        #pragma unroll
        for (int j = 0; j < 8; j++) {
            S[j][0] = __expf(S[j][0] - mn0); S[j][1] = __expf(S[j][1] - mn0);
            S[j][2] = __expf(S[j][2] - mn1); S[j][3] = __expf(S[j][3] - mn1);
            sum0 += S[j][0] + S[j][1];
            sum1 += S[j][2] + S[j][3];
        }
        sum0 = quadSum(sum0); sum1 = quadSum(sum1);
        l0 = l0 * f0 + sum0; l1 = l1 * f1 + sum1;
        m0 = mn0; m1 = mn1;
        #pragma unroll
        for (int j = 0; j < 8; j++) {
            O[j][0] *= f0; O[j][1] *= f0; O[j][2] *= f1; O[j][3] *= f1;
        }

        // PV: P (regs->half) @ V (ldmatrix.trans), accumulate into O
        #pragma unroll
        for (int s16 = 0; s16 < 4; s16++) {
            uint32_t pa[4];
            pa[0] = packh2(S[s16 * 2 + 0][0], S[s16 * 2 + 0][1]);
            pa[1] = packh2(S[s16 * 2 + 0][2], S[s16 * 2 + 0][3]);
            pa[2] = packh2(S[s16 * 2 + 1][0], S[s16 * 2 + 1][1]);
            pa[3] = packh2(S[s16 * 2 + 1][2], S[s16 * 2 + 1][3]);
            #pragma unroll
            for (int nb = 0; nb < 4; nb++) {
                uint32_t v0, v1, v2, v3;
                uint32_t addr = vsb + (s16 * 16 + lrow) * 144 + (nb * 16 + lkb) * 2;
                LDMX4T(v0, v1, v2, v3, addr);
                MMA16816(O[nb * 2 + 0], pa, v0, v1);
                MMA16816(O[nb * 2 + 1], pa, v2, v3);
            }
        }
        st = st == 2 ? 0 : st + 1;
        stn = stn == 2 ? 0 : stn + 1;
    }

    // normalize + write (half)
    float inv0 = 1.f / l0, inv1 = 1.f / l1;
    int r = lane >> 2;
    int grow0 = s * 1024 + q0 + wq0 + r;
    __half* Ob = g_attnout_h + (size_t)grow0 * 1024 + h * 64;
    #pragma unroll
    for (int j = 0; j < 8; j++) {
        int colo = j * 8 + (lane & 3) * 2;
        *(__half2*)(Ob + colo)            = __floats2half2_rn(O[j][0] * inv0, O[j][1] * inv0);
        *(__half2*)(Ob + 8 * 1024 + colo) = __floats2half2_rn(O[j][2] * inv1, O[j][3] * inv1);
    }
}

// ---------------- orchestration ----------------
extern "C" void kernel_launch(void* const* d_in, const int* in_sizes, int n_in,
                              void* d_out, int out_size) {
    const float* x           = (const float*)d_in[0];
    const float* c           = (const float*)d_in[1];
    const float* attn_qkv_w  = (const float*)d_in[2];
    const float* attn_qkv_b  = (const float*)d_in[3];
    const float* attn_proj_w = (const float*)d_in[4];
    const float* attn_proj_b = (const float*)d_in[5];
    const float* crs_qkv_w   = (const float*)d_in[6];
    const float* crs_qkv_b   = (const float*)d_in[7];
    const float* crs_proj_w  = (const float*)d_in[8];
    const float* crs_proj_b  = (const float*)d_in[9];
    const float* mlp_fc1_w   = (const float*)d_in[10];
    const float* mlp_fc1_b   = (const float*)d_in[11];
    const float* mlp_fc2_w   = (const float*)d_in[12];
    const float* mlp_fc2_b   = (const float*)d_in[13];
    const float* ada_w       = (const float*)d_in[14];
    const float* ada_b       = (const float*)d_in[15];
    float* out = (float*)d_out;

    __half *qkv, *xln, *attnout, *hbuf, *wt;
    cudaGetSymbolAddress((void**)&qkv, g_qkv_h);
    cudaGetSymbolAddress((void**)&xln, g_xln_h);
    cudaGetSymbolAddress((void**)&attnout, g_attnout_h);
    cudaGetSymbolAddress((void**)&hbuf, g_hbuf_h);
    cudaGetSymbolAddress((void**)&wt, g_wt);

    const int HS = 110592;        // hgemm: 3 stages x 36864
    const int FS = 55296;         // flash: 3 stages x 18432
    cudaFuncSetAttribute(hgemm<0, 1>, cudaFuncAttributeMaxDynamicSharedMemorySize, HS);
    cudaFuncSetAttribute(hgemm<1, 1>, cudaFuncAttributeMaxDynamicSharedMemorySize, HS);
    cudaFuncSetAttribute(hgemm<2, 0>, cudaFuncAttributeMaxDynamicSharedMemorySize, HS);
    cudaFuncSetAttribute(flash_attn, cudaFuncAttributeMaxDynamicSharedMemorySize, FS);

    dim3 tb(32, 8);
    // launch 1: qkv + proj weights (3072+3072+1024+1024 = 8192 blocks)
    transpose_multi<<<8192, tb>>>(
        attn_qkv_w,  wt + WT_ATTN_QKV,  1024, 3072, 3072,
        crs_qkv_w,   wt + WT_CRS_QKV,   1024, 3072, 6144,
        attn_proj_w, wt + WT_ATTN_PROJ, 1024, 1024, 7168,
        crs_proj_w,  wt + WT_CRS_PROJ,  1024, 1024, 8192);
    // launch 2: fc1 + fc2 (4096+4096 = 8192 blocks)
    transpose_multi<<<8192, tb>>>(
        mlp_fc1_w, wt + WT_FC1, 1024, 4096, 4096,
        mlp_fc2_w, wt + WT_FC2, 4096, 1024, 8192,
        mlp_fc2_w, wt + WT_FC2, 4096, 1024, 8192,
        mlp_fc2_w, wt + WT_FC2, 4096, 1024, 8192);

    mod_kernel<<<dim3(36, 4), 256>>>(c, ada_w, ada_b);                       // launch 3

    // ---- self-attention (MSA): shOff=0, gate off=2048 ----
    ln_mod_kernel<<<4096, 256>>>(x, xln, 0);                                 // launch 4
    hgemm<0, 1><<<dim3(24, 32), 256, HS>>>(xln, wt + WT_ATTN_QKV, qkv, 1024, 3072,
                                           attn_qkv_b, nullptr, 0);          // launch 5
    flash_attn<<<dim3(8, 64), 256, FS>>>(0);                                 // launch 6 (ncu)
    hgemm<2, 0><<<dim3(8, 32), 256, HS>>>(attnout, wt + WT_ATTN_PROJ, out, 1024, 1024,
                                          attn_proj_b, x, 2048);

    // ---- cross-attention (MCA): LN reads post-MSA, residual base = original x ----
    ln_mod_kernel<<<4096, 256>>>(out, xln, 3072);
    hgemm<0, 1><<<dim3(24, 32), 256, HS>>>(xln, wt + WT_CRS_QKV, qkv, 1024, 3072,
                                           crs_qkv_b, nullptr, 0);
    flash_attn<<<dim3(8, 64), 256, FS>>>(1);
    hgemm<2, 0><<<dim3(8, 32), 256, HS>>>(attnout, wt + WT_CRS_PROJ, out, 1024, 1024,
                                          crs_proj_b, x, 5120);

    // ---- MLP: shOff=6144, gate off=8192 ----
    ln_mod_kernel<<<4096, 256>>>(out, xln, 6144);
    hgemm<1, 1><<<dim3(32, 32), 256, HS>>>(xln, wt + WT_FC1, hbuf, 1024, 4096,
                                           mlp_fc1_b, nullptr, 0);
    hgemm<2, 0><<<dim3(8, 32), 256, HS>>>(hbuf, wt + WT_FC2, out, 4096, 1024,
                                          mlp_fc2_b, out, 8192);
}